// round 6
// baseline (speedup 1.0000x reference)
#include <cuda_runtime.h>
#include <cuda_bf16.h>
#include <math.h>
#include <stdint.h>

#define BB 4
#define SS 2048
#define EE 1024
#define HH 16
#define DD 64
#define MM (BB*SS)

// Projected q, k, v fp32: [B*S, E] row-major (col = h*64 + d)
__device__ float g_q[MM * EE];
__device__ float g_k[MM * EE];
__device__ float g_v[MM * EE];

// bf16 split planes of the *inputs* (for proj GEMMs)
__device__ uint16_t g_sa[3][3][MM * EE];
__device__ uint16_t g_sw[3][3][EE * EE];

// bf16 split planes of projected q/k: [plane][B*S, E]
__device__ uint16_t g_qp[3][MM * EE];
__device__ uint16_t g_kp[3][MM * EE];
// bf16 split planes of projected v, TRANSPOSED: [plane][b][h][d][s]
__device__ uint16_t g_vt[2][(size_t)BB * HH * DD * SS];

// ===========================================================================
// helpers
// ===========================================================================
__device__ __forceinline__ uint32_t smem_u32(const void* p) {
    uint32_t a;
    asm("{ .reg .u64 t; cvta.to.shared.u64 t, %1; cvt.u32.u64 %0, t; }"
        : "=r"(a) : "l"(p));
    return a;
}
__device__ __forceinline__ uint32_t sw128(uint32_t off) {
    return off ^ ((off >> 3) & 0x70);
}
__device__ __forceinline__ void split3(float x, uint16_t& b0, uint16_t& b1, uint16_t& b2) {
    __nv_bfloat16 h0 = __float2bfloat16_rn(x);
    float r = x - __bfloat162float(h0);
    __nv_bfloat16 h1 = __float2bfloat16_rn(r);
    r -= __bfloat162float(h1);
    __nv_bfloat16 h2 = __float2bfloat16_rn(r);
    b0 = __bfloat16_as_ushort(h0);
    b1 = __bfloat16_as_ushort(h1);
    b2 = __bfloat16_as_ushort(h2);
}
__device__ __forceinline__ void split2(float x, uint16_t& b0, uint16_t& b1) {
    __nv_bfloat16 h0 = __float2bfloat16_rn(x);
    float r = x - __bfloat162float(h0);
    __nv_bfloat16 h1 = __float2bfloat16_rn(r);
    b0 = __bfloat16_as_ushort(h0);
    b1 = __bfloat16_as_ushort(h1);
}
__device__ __forceinline__ void ldsm4(uint32_t* r, uint32_t addr) {
    asm volatile("ldmatrix.sync.aligned.m8n8.x4.shared.b16 {%0,%1,%2,%3}, [%4];"
        : "=r"(r[0]), "=r"(r[1]), "=r"(r[2]), "=r"(r[3]) : "r"(addr));
}
__device__ __forceinline__ void mma16816(float* c, const uint32_t* a,
                                         uint32_t b0, uint32_t b1) {
    asm volatile("mma.sync.aligned.m16n8k16.row.col.f32.bf16.bf16.f32 "
        "{%0,%1,%2,%3}, {%4,%5,%6,%7}, {%8,%9}, {%0,%1,%2,%3};"
        : "+f"(c[0]), "+f"(c[1]), "+f"(c[2]), "+f"(c[3])
        : "r"(a[0]), "r"(a[1]), "r"(a[2]), "r"(a[3]), "r"(b0), "r"(b1));
}
__device__ __forceinline__ void mma16816_z(float* d, const uint32_t* a,
                                           uint32_t b0, uint32_t b1) {
    asm volatile("mma.sync.aligned.m16n8k16.row.col.f32.bf16.bf16.f32 "
        "{%0,%1,%2,%3}, {%4,%5,%6,%7}, {%8,%9}, {%10,%11,%12,%13};"
        : "=f"(d[0]), "=f"(d[1]), "=f"(d[2]), "=f"(d[3])
        : "r"(a[0]), "r"(a[1]), "r"(a[2]), "r"(a[3]), "r"(b0), "r"(b1),
          "f"(0.0f), "f"(0.0f), "f"(0.0f), "f"(0.0f));
}
#define CPASYNC16(s, g) \
    asm volatile("cp.async.cg.shared.global [%0], [%1], 16;" :: "r"(s), "l"(g))
#define CP_COMMIT() asm volatile("cp.async.commit_group;" ::: "memory")
#define CP_WAIT1()  asm volatile("cp.async.wait_group 1;" ::: "memory")
#define CP_WAIT0()  asm volatile("cp.async.wait_group 0;" ::: "memory")

// ===========================================================================
// Split conversion kernels
// ===========================================================================
__global__ __launch_bounds__(256)
void split_act(const float* __restrict__ q, const float* __restrict__ k,
               const float* __restrict__ v)
{
    const int z = blockIdx.y;
    const float* src = (z == 0) ? q : (z == 1) ? k : v;
    const size_t i = ((size_t)blockIdx.x * 256 + threadIdx.x) * 4;
    const float4 x = *(const float4*)(src + i);
    uint16_t b0[4], b1[4], b2[4];
    split3(x.x, b0[0], b1[0], b2[0]);
    split3(x.y, b0[1], b1[1], b2[1]);
    split3(x.z, b0[2], b1[2], b2[2]);
    split3(x.w, b0[3], b1[3], b2[3]);
    *(ushort4*)&g_sa[z][0][i] = make_ushort4(b0[0], b0[1], b0[2], b0[3]);
    *(ushort4*)&g_sa[z][1][i] = make_ushort4(b1[0], b1[1], b1[2], b1[3]);
    *(ushort4*)&g_sa[z][2][i] = make_ushort4(b2[0], b2[1], b2[2], b2[3]);
}

__global__ __launch_bounds__(256)
void split_w(const float* __restrict__ wq, const float* __restrict__ wk,
             const float* __restrict__ wv)
{
    const int z = blockIdx.y;
    const float* src = (z == 0) ? wq : (z == 1) ? wk : wv;
    const size_t i = ((size_t)blockIdx.x * 256 + threadIdx.x) * 4;
    const float4 x = *(const float4*)(src + i);
    uint16_t b0[4], b1[4], b2[4];
    split3(x.x, b0[0], b1[0], b2[0]);
    split3(x.y, b0[1], b1[1], b2[1]);
    split3(x.z, b0[2], b1[2], b2[2]);
    split3(x.w, b0[3], b1[3], b2[3]);
    *(ushort4*)&g_sw[z][0][i] = make_ushort4(b0[0], b0[1], b0[2], b0[3]);
    *(ushort4*)&g_sw[z][1][i] = make_ushort4(b1[0], b1[1], b1[2], b1[3]);
    *(ushort4*)&g_sw[z][2][i] = make_ushort4(b2[0], b2[1], b2[2], b2[3]);
}

// Split projected q/k into 3 bf16 planes (same [B*S,E] layout)
__global__ __launch_bounds__(256)
void split_qk()
{
    const int z = blockIdx.y;  // 0=q, 1=k
    const float* src = z ? g_k : g_q;
    const size_t i = ((size_t)blockIdx.x * 256 + threadIdx.x) * 4;
    const float4 x = *(const float4*)(src + i);
    uint16_t b0[4], b1[4], b2[4];
    split3(x.x, b0[0], b1[0], b2[0]);
    split3(x.y, b0[1], b1[1], b2[1]);
    split3(x.z, b0[2], b1[2], b2[2]);
    split3(x.w, b0[3], b1[3], b2[3]);
    uint16_t* p0 = z ? g_kp[0] : g_qp[0];
    uint16_t* p1 = z ? g_kp[1] : g_qp[1];
    uint16_t* p2 = z ? g_kp[2] : g_qp[2];
    *(ushort4*)&p0[i] = make_ushort4(b0[0], b0[1], b0[2], b0[3]);
    *(ushort4*)&p1[i] = make_ushort4(b1[0], b1[1], b1[2], b1[3]);
    *(ushort4*)&p2[i] = make_ushort4(b2[0], b2[1], b2[2], b2[3]);
}

// Transpose projected v per (b,h) and split into 2 bf16 planes [b][h][d][s]
__global__ __launch_bounds__(256)
void split_vt()
{
    __shared__ float ts[64][65];
    const int s0 = blockIdx.x * 64;
    const int bh = blockIdx.y;          // b*HH + h
    const int b = bh >> 4, h = bh & 15;
    const int t = threadIdx.x;

#pragma unroll
    for (int i = 0; i < 4; i++) {
        const int e = t + i * 256;      // 0..1023 float4s
        const int sl = e >> 4;
        const int d4 = (e & 15) * 4;
        const float4 x = *(const float4*)(g_v
            + (size_t)(b * SS + s0 + sl) * EE + h * 64 + d4);
        ts[sl][d4 + 0] = x.x; ts[sl][d4 + 1] = x.y;
        ts[sl][d4 + 2] = x.z; ts[sl][d4 + 3] = x.w;
    }
    __syncthreads();

#pragma unroll
    for (int i = 0; i < 4; i++) {
        const int e = t + i * 256;
        const int d  = e >> 4;
        const int s4 = (e & 15) * 4;
        uint16_t a0[4], a1[4];
#pragma unroll
        for (int j = 0; j < 4; j++)
            split2(ts[s4 + j][d], a0[j], a1[j]);
        const size_t o = ((size_t)bh * DD + d) * SS + s0 + s4;
        *(ushort4*)&g_vt[0][o] = make_ushort4(a0[0], a0[1], a0[2], a0[3]);
        *(ushort4*)&g_vt[1][o] = make_ushort4(a1[0], a1[1], a1[2], a1[3]);
    }
}

// ===========================================================================
// Projection GEMM via mma.sync bf16x6 (unchanged from R5 — WIN).
// ===========================================================================
#define TILE_B   16384
#define STAGE_B  (6 * TILE_B)
#define PROJ_SMEM (2 * STAGE_B)
#define KT_STEPS 16

__global__ __launch_bounds__(256, 1)
void proj_mma(const float* __restrict__ bq, const float* __restrict__ bk,
              const float* __restrict__ bv,
              float* __restrict__ Cq, float* __restrict__ Ck,
              float* __restrict__ Cv)
{
    extern __shared__ char smem[];
    const uint32_t sb = smem_u32(smem);
    const int tid = threadIdx.x;
    const int wid = tid >> 5;
    const int l   = tid & 31;
    const int wm = wid >> 2;
    const int wn = wid & 3;

    const int z  = blockIdx.z;
    const int bn = blockIdx.x * 128;
    const int bm = blockIdx.y * 128;
    const float* bias = (z == 0) ? bq : (z == 1) ? bk : bv;
    float*       C    = (z == 0) ? Cq : (z == 1) ? Ck : Cv;

    uint32_t swA[4], swB[2];
#pragma unroll
    for (int mi = 0; mi < 4; mi++)
        swA[mi] = sw128((uint32_t)((wm * 64 + mi * 16 + (l & 15)) * 128
                                   + ((l >> 4) << 4)));
#pragma unroll
    for (int nh = 0; nh < 2; nh++)
        swB[nh] = sw128((uint32_t)((wn * 32 + nh * 16 + ((l >> 4) & 1) * 8
                                    + (l & 7)) * 128 + (((l >> 3) & 1) << 4)));

    float accH[4][4][4];
    float accL[4][4][4];
#pragma unroll
    for (int mi = 0; mi < 4; mi++)
#pragma unroll
        for (int ni = 0; ni < 4; ni++)
#pragma unroll
            for (int c = 0; c < 4; c++) {
                accH[mi][ni][c] = 0.0f;
                accL[mi][ni][c] = 0.0f;
            }

    auto load_stage = [&](int kt, int st) {
        const uint32_t stage = sb + st * STAGE_B;
#pragma unroll
        for (int i = 0; i < 24; i++) {
            const int idx = tid + i * 256;
            const int plane = idx >> 10;
            const int chunk = idx & 1023;
            const int r = chunk >> 3;
            const int c = chunk & 7;
            const uint16_t* gp = (plane < 3)
                ? &g_sa[z][plane][(size_t)(bm + r) * EE + kt * 64 + c * 8]
                : &g_sw[z][plane - 3][(size_t)(bn + r) * EE + kt * 64 + c * 8];
            const uint32_t s = stage + plane * TILE_B + sw128((uint32_t)(r * 128 + c * 16));
            CPASYNC16(s, gp);
        }
        CP_COMMIT();
    };

    load_stage(0, 0);

    const int pa[5] = {1, 0, 2, 1, 0};
    const int pb[5] = {0, 1, 0, 1, 2};

    for (int kt = 0; kt < KT_STEPS; kt++) {
        if (kt + 1 < KT_STEPS) {
            load_stage(kt + 1, (kt + 1) & 1);
            CP_WAIT1();
        } else {
            CP_WAIT0();
        }
        __syncthreads();

        const uint32_t As = sb + (kt & 1) * STAGE_B;
        const uint32_t Bs = As + 3 * TILE_B;

#pragma unroll
        for (int ks = 0; ks < 4; ks++) {
            const uint32_t kx = (uint32_t)(ks << 5);
            uint32_t a[4][4], b[2][4];
#pragma unroll
            for (int mi = 0; mi < 4; mi++)
                ldsm4(a[mi], As + (swA[mi] ^ kx));
#pragma unroll
            for (int nh = 0; nh < 2; nh++)
                ldsm4(b[nh], Bs + (swB[nh] ^ kx));
#pragma unroll
            for (int mi = 0; mi < 4; mi++) {
#pragma unroll
                for (int ni = 0; ni < 4; ni++) {
                    float t[4];
                    const uint32_t bb0 = b[ni >> 1][(ni & 1) * 2];
                    const uint32_t bb1 = b[ni >> 1][(ni & 1) * 2 + 1];
                    mma16816_z(t, a[mi], bb0, bb1);
                    accH[mi][ni][0] += t[0];
                    accH[mi][ni][1] += t[1];
                    accH[mi][ni][2] += t[2];
                    accH[mi][ni][3] += t[3];
                }
            }
        }

#pragma unroll
        for (int p = 0; p < 5; p++) {
            const uint32_t at = As + pa[p] * TILE_B;
            const uint32_t bt = Bs + pb[p] * TILE_B;
#pragma unroll
            for (int ks = 0; ks < 4; ks++) {
                const uint32_t kx = (uint32_t)(ks << 5);
                uint32_t a[4][4], b[2][4];
#pragma unroll
                for (int mi = 0; mi < 4; mi++)
                    ldsm4(a[mi], at + (swA[mi] ^ kx));
#pragma unroll
                for (int nh = 0; nh < 2; nh++)
                    ldsm4(b[nh], bt + (swB[nh] ^ kx));
#pragma unroll
                for (int mi = 0; mi < 4; mi++) {
                    mma16816(accL[mi][0], a[mi], b[0][0], b[0][1]);
                    mma16816(accL[mi][1], a[mi], b[0][2], b[0][3]);
                    mma16816(accL[mi][2], a[mi], b[1][0], b[1][1]);
                    mma16816(accL[mi][3], a[mi], b[1][2], b[1][3]);
                }
            }
        }
        __syncthreads();
    }

#pragma unroll
    for (int mi = 0; mi < 4; mi++) {
        const int r0 = bm + wm * 64 + mi * 16 + (l >> 2);
#pragma unroll
        for (int ni = 0; ni < 4; ni++) {
            const int cb = bn + wn * 32 + ni * 8 + 2 * (l & 3);
            const float bx = bias[cb], by = bias[cb + 1];
            float2 v0 = make_float2(accH[mi][ni][0] + accL[mi][ni][0] + bx,
                                    accH[mi][ni][1] + accL[mi][ni][1] + by);
            float2 v1 = make_float2(accH[mi][ni][2] + accL[mi][ni][2] + bx,
                                    accH[mi][ni][3] + accL[mi][ni][3] + by);
            *(float2*)(C + (size_t)r0 * EE + cb) = v0;
            *(float2*)(C + (size_t)(r0 + 8) * EE + cb) = v1;
        }
    }
}

// ===========================================================================
// Flash attention via mma.sync bf16-split.
// CTA: (b, h, 128 q-rows). k-tile = 64 keys. 8 warps, warp = 16 q-rows x 64.
// QK: 6 chains (main C=0 + fp32 drain, 5 corrections -> accL), floor, online
// softmax (rows warp-private, quad shfl). P -> 2 bf16 planes in warp-private
// smem. PV: 3 chains ((p0,v0) drained into o_H; (p1,v0),(p0,v1) -> accL).
// ===========================================================================
#define AQ_OFF   0                     // Q planes: 3 x 16384
#define AK_OFF   49152                 // stages: 2 x (3x8192 K + 2x8192 V)
#define AST_B    40960
#define AP_OFF   (49152 + 2 * AST_B)   // P planes: 2 x 16384
#define ATTN_SMEM (AP_OFF + 2 * 16384) // 163840

__global__ __launch_bounds__(256, 1)
void attn_mma(float* __restrict__ Out)
{
    extern __shared__ char smem[];
    const uint32_t sb = smem_u32(smem);
    const int tid = threadIdx.x;
    const int w   = tid >> 5;
    const int l   = tid & 31;

    const int b  = blockIdx.z;
    const int h  = blockIdx.y;
    const int q0 = blockIdx.x * 128;
    const int hofs = h * 64;
    const size_t rowbase = (size_t)b * SS;           // token row base
    const size_t vtbase  = (size_t)(b * HH + h) * DD; // vt row base

    // ldmatrix lane offsets
    const uint32_t offA = sw128((uint32_t)((w * 16 + (l & 15)) * 128
                                           + ((l >> 4) << 4)));
    uint32_t offB[4];
#pragma unroll
    for (int g = 0; g < 4; g++)
        offB[g] = sw128((uint32_t)((g * 16 + ((l >> 4) & 1) * 8 + (l & 7)) * 128
                                   + (((l >> 3) & 1) << 4)));
    // P store: rows rlo=w*16+(l>>2), rhi=+8; 4B at chunk ni
    const int prlo = w * 16 + (l >> 2);
    const uint32_t pst_lo = (uint32_t)(prlo * 128 + (l & 3) * 4);
    const uint32_t pst_hi = (uint32_t)((prlo + 8) * 128 + (l & 3) * 4);

    // ---- load Q planes + stage 0 ----
#pragma unroll
    for (int i = 0; i < 12; i++) {
        const int idx = tid + i * 256;           // 0..3071
        const int plane = idx >> 10;
        const int rem = idx & 1023;
        const int r = rem >> 3, c = rem & 7;
        const uint16_t* src = &g_qp[plane][(rowbase + q0 + r) * EE + hofs + c * 8];
        CPASYNC16(sb + AQ_OFF + plane * 16384 + sw128((uint32_t)(r * 128 + c * 16)), src);
    }
    auto load_kv = [&](int kt, int st) {
        const uint32_t kb = sb + AK_OFF + st * AST_B;
#pragma unroll
        for (int i = 0; i < 6; i++) {
            const int idx = tid + i * 256;       // 0..1535
            const int plane = idx >> 9;
            const int rem = idx & 511;
            const int r = rem >> 3, c = rem & 7;
            const uint16_t* src = &g_kp[plane][(rowbase + kt * 64 + r) * EE + hofs + c * 8];
            CPASYNC16(kb + plane * 8192 + sw128((uint32_t)(r * 128 + c * 16)), src);
        }
#pragma unroll
        for (int i = 0; i < 4; i++) {
            const int idx = tid + i * 256;       // 0..1023
            const int plane = idx >> 9;
            const int rem = idx & 511;
            const int r = rem >> 3, c = rem & 7;
            const uint16_t* src = &g_vt[plane][(vtbase + r) * SS + kt * 64 + c * 8];
            CPASYNC16(kb + 24576 + plane * 8192 + sw128((uint32_t)(r * 128 + c * 16)), src);
        }
        CP_COMMIT();
    };
    load_kv(0, 0);

    float oH[8][4];
    float m0 = -1e30f, m1 = -1e30f, ls0 = 0.0f, ls1 = 0.0f;
#pragma unroll
    for (int ni = 0; ni < 8; ni++)
#pragma unroll
        for (int c = 0; c < 4; c++) oH[ni][c] = 0.0f;

    const int pa[5] = {1, 0, 2, 1, 0};
    const int pb[5] = {0, 1, 0, 1, 2};

    for (int kt = 0; kt < SS / 64; kt++) {
        if (kt + 1 < SS / 64) {
            load_kv(kt + 1, (kt + 1) & 1);
            CP_WAIT1();
        } else {
            CP_WAIT0();
        }
        __syncthreads();

        const uint32_t Ks = sb + AK_OFF + (kt & 1) * AST_B;
        const uint32_t Vs = Ks + 24576;
        const uint32_t Qs = sb + AQ_OFF;

        // ---- S = QK^T (bf16x6 emulated fp32) ----
        float accH[8][4], accL[8][4];
#pragma unroll
        for (int ni = 0; ni < 8; ni++)
#pragma unroll
            for (int c = 0; c < 4; c++) { accH[ni][c] = 0.0f; accL[ni][c] = 0.0f; }

#pragma unroll
        for (int ks = 0; ks < 4; ks++) {
            const uint32_t kx = (uint32_t)(ks << 5);
            uint32_t aq[3][4];
#pragma unroll
            for (int p = 0; p < 3; p++)
                ldsm4(aq[p], Qs + p * 16384 + (offA ^ kx));
#pragma unroll
            for (int g = 0; g < 4; g++) {
                uint32_t bk[3][4];
#pragma unroll
                for (int p = 0; p < 3; p++)
                    ldsm4(bk[p], Ks + p * 8192 + (offB[g] ^ kx));
                // main chain (0,0): C=0 + drain
                {
                    float t[4];
                    mma16816_z(t, aq[0], bk[0][0], bk[0][1]);
                    accH[g*2][0] += t[0]; accH[g*2][1] += t[1];
                    accH[g*2][2] += t[2]; accH[g*2][3] += t[3];
                    mma16816_z(t, aq[0], bk[0][2], bk[0][3]);
                    accH[g*2+1][0] += t[0]; accH[g*2+1][1] += t[1];
                    accH[g*2+1][2] += t[2]; accH[g*2+1][3] += t[3];
                }
                // corrections
#pragma unroll
                for (int p = 0; p < 5; p++) {
                    mma16816(accL[g*2],   aq[pa[p]], bk[pb[p]][0], bk[pb[p]][1]);
                    mma16816(accL[g*2+1], aq[pa[p]], bk[pb[p]][2], bk[pb[p]][3]);
                }
            }
        }

        // ---- floor(S/8), online softmax ----
        float S[8][4];
        float mt0 = -1e30f, mt1 = -1e30f;
#pragma unroll
        for (int ni = 0; ni < 8; ni++) {
            S[ni][0] = floorf((accH[ni][0] + accL[ni][0]) * 0.125f);
            S[ni][1] = floorf((accH[ni][1] + accL[ni][1]) * 0.125f);
            S[ni][2] = floorf((accH[ni][2] + accL[ni][2]) * 0.125f);
            S[ni][3] = floorf((accH[ni][3] + accL[ni][3]) * 0.125f);
            mt0 = fmaxf(mt0, fmaxf(S[ni][0], S[ni][1]));
            mt1 = fmaxf(mt1, fmaxf(S[ni][2], S[ni][3]));
        }
#pragma unroll
        for (int off = 1; off <= 2; off <<= 1) {
            mt0 = fmaxf(mt0, __shfl_xor_sync(0xffffffffu, mt0, off));
            mt1 = fmaxf(mt1, __shfl_xor_sync(0xffffffffu, mt1, off));
        }
        const float mn0 = fmaxf(m0, mt0), mn1 = fmaxf(m1, mt1);
        const float sc0 = __expf(m0 - mn0), sc1 = __expf(m1 - mn1);
        m0 = mn0; m1 = mn1;

        float rs0 = 0.0f, rs1 = 0.0f;
#pragma unroll
        for (int ni = 0; ni < 8; ni++) {
            S[ni][0] = __expf(S[ni][0] - mn0);
            S[ni][1] = __expf(S[ni][1] - mn0);
            S[ni][2] = __expf(S[ni][2] - mn1);
            S[ni][3] = __expf(S[ni][3] - mn1);
            rs0 += S[ni][0] + S[ni][1];
            rs1 += S[ni][2] + S[ni][3];
        }
#pragma unroll
        for (int off = 1; off <= 2; off <<= 1) {
            rs0 += __shfl_xor_sync(0xffffffffu, rs0, off);
            rs1 += __shfl_xor_sync(0xffffffffu, rs1, off);
        }
        ls0 = ls0 * sc0 + rs0;
        ls1 = ls1 * sc1 + rs1;
#pragma unroll
        for (int ni = 0; ni < 8; ni++) {
            oH[ni][0] *= sc0; oH[ni][1] *= sc0;
            oH[ni][2] *= sc1; oH[ni][3] *= sc1;
        }

        // ---- P -> 2 bf16 planes (warp-private smem rows) ----
#pragma unroll
        for (int ni = 0; ni < 8; ni++) {
            uint16_t p00, p01, p10, p11, q00, q01, q10, q11;
            split2(S[ni][0], p00, q00);
            split2(S[ni][1], p01, q01);
            split2(S[ni][2], p10, q10);
            split2(S[ni][3], p11, q11);
            const uint32_t clo = sw128(pst_lo + ni * 16);
            const uint32_t chi = sw128(pst_hi + ni * 16);
            *(uint32_t*)(smem + AP_OFF + clo) = (uint32_t)p00 | ((uint32_t)p01 << 16);
            *(uint32_t*)(smem + AP_OFF + chi) = (uint32_t)p10 | ((uint32_t)p11 << 16);
            *(uint32_t*)(smem + AP_OFF + 16384 + clo) = (uint32_t)q00 | ((uint32_t)q01 << 16);
            *(uint32_t*)(smem + AP_OFF + 16384 + chi) = (uint32_t)q10 | ((uint32_t)q11 << 16);
        }
        __syncwarp();

        // ---- O += P V (bf16x3 emulated) ----
        float accP[8][4];
#pragma unroll
        for (int ni = 0; ni < 8; ni++)
#pragma unroll
            for (int c = 0; c < 4; c++) accP[ni][c] = 0.0f;

        const uint32_t Ps = sb + AP_OFF;
#pragma unroll
        for (int ks = 0; ks < 4; ks++) {
            const uint32_t kx = (uint32_t)(ks << 5);
            uint32_t ap0[4], ap1[4];
            ldsm4(ap0, Ps + (offA ^ kx));
            ldsm4(ap1, Ps + 16384 + (offA ^ kx));
#pragma unroll
            for (int g = 0; g < 4; g++) {
                uint32_t bv0[4], bv1[4];
                ldsm4(bv0, Vs + (offB[g] ^ kx));
                ldsm4(bv1, Vs + 8192 + (offB[g] ^ kx));
                {
                    float t[4];
                    mma16816_z(t, ap0, bv0[0], bv0[1]);
                    oH[g*2][0] += t[0]; oH[g*2][1] += t[1];
                    oH[g*2][2] += t[2]; oH[g*2][3] += t[3];
                    mma16816_z(t, ap0, bv0[2], bv0[3]);
                    oH[g*2+1][0] += t[0]; oH[g*2+1][1] += t[1];
                    oH[g*2+1][2] += t[2]; oH[g*2+1][3] += t[3];
                }
                mma16816(accP[g*2],   ap1, bv0[0], bv0[1]);
                mma16816(accP[g*2+1], ap1, bv0[2], bv0[3]);
                mma16816(accP[g*2],   ap0, bv1[0], bv1[1]);
                mma16816(accP[g*2+1], ap0, bv1[2], bv1[3]);
            }
        }
#pragma unroll
        for (int ni = 0; ni < 8; ni++)
#pragma unroll
            for (int c = 0; c < 4; c++) oH[ni][c] += accP[ni][c];

        __syncthreads();  // stage reuse barrier (K/V of this kt consumed)
    }

    // ---- epilogue ----
    const float inv0 = 1.0f / ls0;
    const float inv1 = 1.0f / ls1;
    const int r0 = q0 + prlo;
#pragma unroll
    for (int ni = 0; ni < 8; ni++) {
        const int cb = hofs + ni * 8 + 2 * (l & 3);
        *(float2*)(Out + (rowbase + r0) * EE + cb) =
            make_float2(oH[ni][0] * inv0, oH[ni][1] * inv0);
        *(float2*)(Out + (rowbase + r0 + 8) * EE + cb) =
            make_float2(oH[ni][2] * inv1, oH[ni][3] * inv1);
    }
}

// ---------------------------------------------------------------------------
extern "C" void kernel_launch(void* const* d_in, const int* in_sizes, int n_in,
                              void* d_out, int out_size)
{
    const float* key   = (const float*)d_in[0];
    const float* query = (const float*)d_in[1];
    const float* value = (const float*)d_in[2];
    const float* Wq    = (const float*)d_in[3];
    const float* bq    = (const float*)d_in[4];
    const float* Wk    = (const float*)d_in[5];
    const float* bk    = (const float*)d_in[6];
    const float* Wv    = (const float*)d_in[7];
    const float* bv    = (const float*)d_in[8];
    float* out = (float*)d_out;

    void *pq = 0, *pk = 0, *pv = 0;
    cudaGetSymbolAddress(&pq, g_q);
    cudaGetSymbolAddress(&pk, g_k);
    cudaGetSymbolAddress(&pv, g_v);

    cudaFuncSetAttribute(proj_mma, cudaFuncAttributeMaxDynamicSharedMemorySize,
                         PROJ_SMEM);
    cudaFuncSetAttribute(attn_mma, cudaFuncAttributeMaxDynamicSharedMemorySize,
                         ATTN_SMEM);

    dim3 sgrid(MM * EE / 1024, 3);
    split_act<<<sgrid, 256>>>(query, key, value);
    dim3 wgrid(EE * EE / 1024, 3);
    split_w<<<wgrid, 256>>>(Wq, Wk, Wv);

    dim3 pgrid(EE / 128, MM / 128, 3);
    proj_mma<<<pgrid, 256, PROJ_SMEM>>>(bq, bk, bv,
                                        (float*)pq, (float*)pk, (float*)pv);

    dim3 qkgrid(MM * EE / 1024, 2);
    split_qk<<<qkgrid, 256>>>();
    dim3 vtgrid(SS / 64, BB * HH);
    split_vt<<<vtgrid, 256>>>();

    dim3 agrid(SS / 128, HH, BB);
    attn_mma<<<agrid, 256, ATTN_SMEM>>>(out);
}

// round 7
// speedup vs baseline: 1.0014x; 1.0014x over previous
#include <cuda_runtime.h>
#include <cuda_bf16.h>
#include <math.h>
#include <stdint.h>

#define BB 4
#define SS 2048
#define EE 1024
#define HH 16
#define DD 64
#define MM (BB*SS)

// Projected q, k, v fp32: [B*S, E] row-major (col = h*64 + d)
__device__ float g_q[MM * EE];
__device__ float g_k[MM * EE];
__device__ float g_v[MM * EE];

// bf16 split planes of the *inputs* (for proj GEMMs)
__device__ uint16_t g_sa[3][3][MM * EE];
__device__ uint16_t g_sw[3][3][EE * EE];

// bf16 split planes of projected q/k: [plane][B*S, E]
__device__ uint16_t g_qp[3][MM * EE];
__device__ uint16_t g_kp[3][MM * EE];
// bf16 split planes of projected v, TRANSPOSED: [plane][b][h][d][s]
__device__ uint16_t g_vt[2][(size_t)BB * HH * DD * SS];

// ===========================================================================
// helpers
// ===========================================================================
__device__ __forceinline__ uint32_t smem_u32(const void* p) {
    uint32_t a;
    asm("{ .reg .u64 t; cvta.to.shared.u64 t, %1; cvt.u32.u64 %0, t; }"
        : "=r"(a) : "l"(p));
    return a;
}
__device__ __forceinline__ uint32_t sw128(uint32_t off) {
    return off ^ ((off >> 3) & 0x70);
}
__device__ __forceinline__ void split3(float x, uint16_t& b0, uint16_t& b1, uint16_t& b2) {
    __nv_bfloat16 h0 = __float2bfloat16_rn(x);
    float r = x - __bfloat162float(h0);
    __nv_bfloat16 h1 = __float2bfloat16_rn(r);
    r -= __bfloat162float(h1);
    __nv_bfloat16 h2 = __float2bfloat16_rn(r);
    b0 = __bfloat16_as_ushort(h0);
    b1 = __bfloat16_as_ushort(h1);
    b2 = __bfloat16_as_ushort(h2);
}
__device__ __forceinline__ void split2(float x, uint16_t& b0, uint16_t& b1) {
    __nv_bfloat16 h0 = __float2bfloat16_rn(x);
    float r = x - __bfloat162float(h0);
    __nv_bfloat16 h1 = __float2bfloat16_rn(r);
    b0 = __bfloat16_as_ushort(h0);
    b1 = __bfloat16_as_ushort(h1);
}
__device__ __forceinline__ void ldsm4(uint32_t* r, uint32_t addr) {
    asm volatile("ldmatrix.sync.aligned.m8n8.x4.shared.b16 {%0,%1,%2,%3}, [%4];"
        : "=r"(r[0]), "=r"(r[1]), "=r"(r[2]), "=r"(r[3]) : "r"(addr));
}
__device__ __forceinline__ void mma16816(float* c, const uint32_t* a,
                                         uint32_t b0, uint32_t b1) {
    asm volatile("mma.sync.aligned.m16n8k16.row.col.f32.bf16.bf16.f32 "
        "{%0,%1,%2,%3}, {%4,%5,%6,%7}, {%8,%9}, {%0,%1,%2,%3};"
        : "+f"(c[0]), "+f"(c[1]), "+f"(c[2]), "+f"(c[3])
        : "r"(a[0]), "r"(a[1]), "r"(a[2]), "r"(a[3]), "r"(b0), "r"(b1));
}
__device__ __forceinline__ void mma16816_z(float* d, const uint32_t* a,
                                           uint32_t b0, uint32_t b1) {
    asm volatile("mma.sync.aligned.m16n8k16.row.col.f32.bf16.bf16.f32 "
        "{%0,%1,%2,%3}, {%4,%5,%6,%7}, {%8,%9}, {%10,%11,%12,%13};"
        : "=f"(d[0]), "=f"(d[1]), "=f"(d[2]), "=f"(d[3])
        : "r"(a[0]), "r"(a[1]), "r"(a[2]), "r"(a[3]), "r"(b0), "r"(b1),
          "f"(0.0f), "f"(0.0f), "f"(0.0f), "f"(0.0f));
}
#define CPASYNC16(s, g) \
    asm volatile("cp.async.cg.shared.global [%0], [%1], 16;" :: "r"(s), "l"(g))
#define CP_COMMIT() asm volatile("cp.async.commit_group;" ::: "memory")
#define CP_WAIT1()  asm volatile("cp.async.wait_group 1;" ::: "memory")
#define CP_WAIT0()  asm volatile("cp.async.wait_group 0;" ::: "memory")

// ===========================================================================
// Split conversion kernels
// ===========================================================================
__global__ __launch_bounds__(256)
void split_act(const float* __restrict__ q, const float* __restrict__ k,
               const float* __restrict__ v)
{
    const int z = blockIdx.y;
    const float* src = (z == 0) ? q : (z == 1) ? k : v;
    const size_t i = ((size_t)blockIdx.x * 256 + threadIdx.x) * 4;
    const float4 x = *(const float4*)(src + i);
    uint16_t b0[4], b1[4], b2[4];
    split3(x.x, b0[0], b1[0], b2[0]);
    split3(x.y, b0[1], b1[1], b2[1]);
    split3(x.z, b0[2], b1[2], b2[2]);
    split3(x.w, b0[3], b1[3], b2[3]);
    *(ushort4*)&g_sa[z][0][i] = make_ushort4(b0[0], b0[1], b0[2], b0[3]);
    *(ushort4*)&g_sa[z][1][i] = make_ushort4(b1[0], b1[1], b1[2], b1[3]);
    *(ushort4*)&g_sa[z][2][i] = make_ushort4(b2[0], b2[1], b2[2], b2[3]);
}

__global__ __launch_bounds__(256)
void split_w(const float* __restrict__ wq, const float* __restrict__ wk,
             const float* __restrict__ wv)
{
    const int z = blockIdx.y;
    const float* src = (z == 0) ? wq : (z == 1) ? wk : wv;
    const size_t i = ((size_t)blockIdx.x * 256 + threadIdx.x) * 4;
    const float4 x = *(const float4*)(src + i);
    uint16_t b0[4], b1[4], b2[4];
    split3(x.x, b0[0], b1[0], b2[0]);
    split3(x.y, b0[1], b1[1], b2[1]);
    split3(x.z, b0[2], b1[2], b2[2]);
    split3(x.w, b0[3], b1[3], b2[3]);
    *(ushort4*)&g_sw[z][0][i] = make_ushort4(b0[0], b0[1], b0[2], b0[3]);
    *(ushort4*)&g_sw[z][1][i] = make_ushort4(b1[0], b1[1], b1[2], b1[3]);
    *(ushort4*)&g_sw[z][2][i] = make_ushort4(b2[0], b2[1], b2[2], b2[3]);
}

// Split projected q/k into 3 bf16 planes (same [B*S,E] layout)
__global__ __launch_bounds__(256)
void split_qk()
{
    const int z = blockIdx.y;  // 0=q, 1=k
    const float* src = z ? g_k : g_q;
    const size_t i = ((size_t)blockIdx.x * 256 + threadIdx.x) * 4;
    const float4 x = *(const float4*)(src + i);
    uint16_t b0[4], b1[4], b2[4];
    split3(x.x, b0[0], b1[0], b2[0]);
    split3(x.y, b0[1], b1[1], b2[1]);
    split3(x.z, b0[2], b1[2], b2[2]);
    split3(x.w, b0[3], b1[3], b2[3]);
    uint16_t* p0 = z ? g_kp[0] : g_qp[0];
    uint16_t* p1 = z ? g_kp[1] : g_qp[1];
    uint16_t* p2 = z ? g_kp[2] : g_qp[2];
    *(ushort4*)&p0[i] = make_ushort4(b0[0], b0[1], b0[2], b0[3]);
    *(ushort4*)&p1[i] = make_ushort4(b1[0], b1[1], b1[2], b1[3]);
    *(ushort4*)&p2[i] = make_ushort4(b2[0], b2[1], b2[2], b2[3]);
}

// Transpose projected v per (b,h) and split into 2 bf16 planes [b][h][d][s]
__global__ __launch_bounds__(256)
void split_vt()
{
    __shared__ float ts[64][65];
    const int s0 = blockIdx.x * 64;
    const int bh = blockIdx.y;          // b*HH + h
    const int b = bh >> 4, h = bh & 15;
    const int t = threadIdx.x;

#pragma unroll
    for (int i = 0; i < 4; i++) {
        const int e = t + i * 256;      // 0..1023 float4s
        const int sl = e >> 4;
        const int d4 = (e & 15) * 4;
        const float4 x = *(const float4*)(g_v
            + (size_t)(b * SS + s0 + sl) * EE + h * 64 + d4);
        ts[sl][d4 + 0] = x.x; ts[sl][d4 + 1] = x.y;
        ts[sl][d4 + 2] = x.z; ts[sl][d4 + 3] = x.w;
    }
    __syncthreads();

#pragma unroll
    for (int i = 0; i < 4; i++) {
        const int e = t + i * 256;
        const int d  = e >> 4;
        const int s4 = (e & 15) * 4;
        uint16_t a0[4], a1[4];
#pragma unroll
        for (int j = 0; j < 4; j++)
            split2(ts[s4 + j][d], a0[j], a1[j]);
        const size_t o = ((size_t)bh * DD + d) * SS + s0 + s4;
        *(ushort4*)&g_vt[0][o] = make_ushort4(a0[0], a0[1], a0[2], a0[3]);
        *(ushort4*)&g_vt[1][o] = make_ushort4(a1[0], a1[1], a1[2], a1[3]);
    }
}

// ===========================================================================
// Projection GEMM via mma.sync bf16x6 (unchanged from R5 — WIN).
// ===========================================================================
#define TILE_B   16384
#define STAGE_B  (6 * TILE_B)
#define PROJ_SMEM (2 * STAGE_B)
#define KT_STEPS 16

__global__ __launch_bounds__(256, 1)
void proj_mma(const float* __restrict__ bq, const float* __restrict__ bk,
              const float* __restrict__ bv,
              float* __restrict__ Cq, float* __restrict__ Ck,
              float* __restrict__ Cv)
{
    extern __shared__ char smem[];
    const uint32_t sb = smem_u32(smem);
    const int tid = threadIdx.x;
    const int wid = tid >> 5;
    const int l   = tid & 31;
    const int wm = wid >> 2;
    const int wn = wid & 3;

    const int z  = blockIdx.z;
    const int bn = blockIdx.x * 128;
    const int bm = blockIdx.y * 128;
    const float* bias = (z == 0) ? bq : (z == 1) ? bk : bv;
    float*       C    = (z == 0) ? Cq : (z == 1) ? Ck : Cv;

    uint32_t swA[4], swB[2];
#pragma unroll
    for (int mi = 0; mi < 4; mi++)
        swA[mi] = sw128((uint32_t)((wm * 64 + mi * 16 + (l & 15)) * 128
                                   + ((l >> 4) << 4)));
#pragma unroll
    for (int nh = 0; nh < 2; nh++)
        swB[nh] = sw128((uint32_t)((wn * 32 + nh * 16 + ((l >> 4) & 1) * 8
                                    + (l & 7)) * 128 + (((l >> 3) & 1) << 4)));

    float accH[4][4][4];
    float accL[4][4][4];
#pragma unroll
    for (int mi = 0; mi < 4; mi++)
#pragma unroll
        for (int ni = 0; ni < 4; ni++)
#pragma unroll
            for (int c = 0; c < 4; c++) {
                accH[mi][ni][c] = 0.0f;
                accL[mi][ni][c] = 0.0f;
            }

    auto load_stage = [&](int kt, int st) {
        const uint32_t stage = sb + st * STAGE_B;
#pragma unroll
        for (int i = 0; i < 24; i++) {
            const int idx = tid + i * 256;
            const int plane = idx >> 10;
            const int chunk = idx & 1023;
            const int r = chunk >> 3;
            const int c = chunk & 7;
            const uint16_t* gp = (plane < 3)
                ? &g_sa[z][plane][(size_t)(bm + r) * EE + kt * 64 + c * 8]
                : &g_sw[z][plane - 3][(size_t)(bn + r) * EE + kt * 64 + c * 8];
            const uint32_t s = stage + plane * TILE_B + sw128((uint32_t)(r * 128 + c * 16));
            CPASYNC16(s, gp);
        }
        CP_COMMIT();
    };

    load_stage(0, 0);

    const int pa[5] = {1, 0, 2, 1, 0};
    const int pb[5] = {0, 1, 0, 1, 2};

    for (int kt = 0; kt < KT_STEPS; kt++) {
        if (kt + 1 < KT_STEPS) {
            load_stage(kt + 1, (kt + 1) & 1);
            CP_WAIT1();
        } else {
            CP_WAIT0();
        }
        __syncthreads();

        const uint32_t As = sb + (kt & 1) * STAGE_B;
        const uint32_t Bs = As + 3 * TILE_B;

#pragma unroll
        for (int ks = 0; ks < 4; ks++) {
            const uint32_t kx = (uint32_t)(ks << 5);
            uint32_t a[4][4], b[2][4];
#pragma unroll
            for (int mi = 0; mi < 4; mi++)
                ldsm4(a[mi], As + (swA[mi] ^ kx));
#pragma unroll
            for (int nh = 0; nh < 2; nh++)
                ldsm4(b[nh], Bs + (swB[nh] ^ kx));
#pragma unroll
            for (int mi = 0; mi < 4; mi++) {
#pragma unroll
                for (int ni = 0; ni < 4; ni++) {
                    float t[4];
                    const uint32_t bb0 = b[ni >> 1][(ni & 1) * 2];
                    const uint32_t bb1 = b[ni >> 1][(ni & 1) * 2 + 1];
                    mma16816_z(t, a[mi], bb0, bb1);
                    accH[mi][ni][0] += t[0];
                    accH[mi][ni][1] += t[1];
                    accH[mi][ni][2] += t[2];
                    accH[mi][ni][3] += t[3];
                }
            }
        }

#pragma unroll
        for (int p = 0; p < 5; p++) {
            const uint32_t at = As + pa[p] * TILE_B;
            const uint32_t bt = Bs + pb[p] * TILE_B;
#pragma unroll
            for (int ks = 0; ks < 4; ks++) {
                const uint32_t kx = (uint32_t)(ks << 5);
                uint32_t a[4][4], b[2][4];
#pragma unroll
                for (int mi = 0; mi < 4; mi++)
                    ldsm4(a[mi], at + (swA[mi] ^ kx));
#pragma unroll
                for (int nh = 0; nh < 2; nh++)
                    ldsm4(b[nh], bt + (swB[nh] ^ kx));
#pragma unroll
                for (int mi = 0; mi < 4; mi++) {
                    mma16816(accL[mi][0], a[mi], b[0][0], b[0][1]);
                    mma16816(accL[mi][1], a[mi], b[0][2], b[0][3]);
                    mma16816(accL[mi][2], a[mi], b[1][0], b[1][1]);
                    mma16816(accL[mi][3], a[mi], b[1][2], b[1][3]);
                }
            }
        }
        __syncthreads();
    }

#pragma unroll
    for (int mi = 0; mi < 4; mi++) {
        const int r0 = bm + wm * 64 + mi * 16 + (l >> 2);
#pragma unroll
        for (int ni = 0; ni < 4; ni++) {
            const int cb = bn + wn * 32 + ni * 8 + 2 * (l & 3);
            const float bx = bias[cb], by = bias[cb + 1];
            float2 v0 = make_float2(accH[mi][ni][0] + accL[mi][ni][0] + bx,
                                    accH[mi][ni][1] + accL[mi][ni][1] + by);
            float2 v1 = make_float2(accH[mi][ni][2] + accL[mi][ni][2] + bx,
                                    accH[mi][ni][3] + accL[mi][ni][3] + by);
            *(float2*)(C + (size_t)r0 * EE + cb) = v0;
            *(float2*)(C + (size_t)(r0 + 8) * EE + cb) = v1;
        }
    }
}

// ===========================================================================
// Flash attention via mma.sync bf16-split.
// CTA: (b, h, 128 q-rows). k-tile = 64 keys. 8 warps, warp = 16 q-rows x 64.
// QK: 6 chains (main C=0 + fp32 drain, 5 corrections -> accL), floor, online
// softmax (rows warp-private, quad shfl). P -> 2 bf16 planes in warp-private
// smem. PV: 3 chains ((p0,v0) drained into o_H; (p1,v0),(p0,v1) -> accL).
// ===========================================================================
#define AQ_OFF   0                     // Q planes: 3 x 16384
#define AK_OFF   49152                 // stages: 2 x (3x8192 K + 2x8192 V)
#define AST_B    40960
#define AP_OFF   (49152 + 2 * AST_B)   // P planes: 2 x 16384
#define ATTN_SMEM (AP_OFF + 2 * 16384) // 163840

__global__ __launch_bounds__(256, 1)
void attn_mma(float* __restrict__ Out)
{
    extern __shared__ char smem[];
    const uint32_t sb = smem_u32(smem);
    const int tid = threadIdx.x;
    const int w   = tid >> 5;
    const int l   = tid & 31;

    const int b  = blockIdx.z;
    const int h  = blockIdx.y;
    const int q0 = blockIdx.x * 128;
    const int hofs = h * 64;
    const size_t rowbase = (size_t)b * SS;           // token row base
    const size_t vtbase  = (size_t)(b * HH + h) * DD; // vt row base

    // ldmatrix lane offsets
    const uint32_t offA = sw128((uint32_t)((w * 16 + (l & 15)) * 128
                                           + ((l >> 4) << 4)));
    uint32_t offB[4];
#pragma unroll
    for (int g = 0; g < 4; g++)
        offB[g] = sw128((uint32_t)((g * 16 + ((l >> 4) & 1) * 8 + (l & 7)) * 128
                                   + (((l >> 3) & 1) << 4)));
    // P store: rows rlo=w*16+(l>>2), rhi=+8; 4B at chunk ni
    const int prlo = w * 16 + (l >> 2);
    const uint32_t pst_lo = (uint32_t)(prlo * 128 + (l & 3) * 4);
    const uint32_t pst_hi = (uint32_t)((prlo + 8) * 128 + (l & 3) * 4);

    // ---- load Q planes + stage 0 ----
#pragma unroll
    for (int i = 0; i < 12; i++) {
        const int idx = tid + i * 256;           // 0..3071
        const int plane = idx >> 10;
        const int rem = idx & 1023;
        const int r = rem >> 3, c = rem & 7;
        const uint16_t* src = &g_qp[plane][(rowbase + q0 + r) * EE + hofs + c * 8];
        CPASYNC16(sb + AQ_OFF + plane * 16384 + sw128((uint32_t)(r * 128 + c * 16)), src);
    }
    auto load_kv = [&](int kt, int st) {
        const uint32_t kb = sb + AK_OFF + st * AST_B;
#pragma unroll
        for (int i = 0; i < 6; i++) {
            const int idx = tid + i * 256;       // 0..1535
            const int plane = idx >> 9;
            const int rem = idx & 511;
            const int r = rem >> 3, c = rem & 7;
            const uint16_t* src = &g_kp[plane][(rowbase + kt * 64 + r) * EE + hofs + c * 8];
            CPASYNC16(kb + plane * 8192 + sw128((uint32_t)(r * 128 + c * 16)), src);
        }
#pragma unroll
        for (int i = 0; i < 4; i++) {
            const int idx = tid + i * 256;       // 0..1023
            const int plane = idx >> 9;
            const int rem = idx & 511;
            const int r = rem >> 3, c = rem & 7;
            const uint16_t* src = &g_vt[plane][(vtbase + r) * SS + kt * 64 + c * 8];
            CPASYNC16(kb + 24576 + plane * 8192 + sw128((uint32_t)(r * 128 + c * 16)), src);
        }
        CP_COMMIT();
    };
    load_kv(0, 0);

    float oH[8][4];
    float m0 = -1e30f, m1 = -1e30f, ls0 = 0.0f, ls1 = 0.0f;
#pragma unroll
    for (int ni = 0; ni < 8; ni++)
#pragma unroll
        for (int c = 0; c < 4; c++) oH[ni][c] = 0.0f;

    const int pa[5] = {1, 0, 2, 1, 0};
    const int pb[5] = {0, 1, 0, 1, 2};

    for (int kt = 0; kt < SS / 64; kt++) {
        if (kt + 1 < SS / 64) {
            load_kv(kt + 1, (kt + 1) & 1);
            CP_WAIT1();
        } else {
            CP_WAIT0();
        }
        __syncthreads();

        const uint32_t Ks = sb + AK_OFF + (kt & 1) * AST_B;
        const uint32_t Vs = Ks + 24576;
        const uint32_t Qs = sb + AQ_OFF;

        // ---- S = QK^T (bf16x6 emulated fp32) ----
        float accH[8][4], accL[8][4];
#pragma unroll
        for (int ni = 0; ni < 8; ni++)
#pragma unroll
            for (int c = 0; c < 4; c++) { accH[ni][c] = 0.0f; accL[ni][c] = 0.0f; }

#pragma unroll
        for (int ks = 0; ks < 4; ks++) {
            const uint32_t kx = (uint32_t)(ks << 5);
            uint32_t aq[3][4];
#pragma unroll
            for (int p = 0; p < 3; p++)
                ldsm4(aq[p], Qs + p * 16384 + (offA ^ kx));
#pragma unroll
            for (int g = 0; g < 4; g++) {
                uint32_t bk[3][4];
#pragma unroll
                for (int p = 0; p < 3; p++)
                    ldsm4(bk[p], Ks + p * 8192 + (offB[g] ^ kx));
                // main chain (0,0): C=0 + drain
                {
                    float t[4];
                    mma16816_z(t, aq[0], bk[0][0], bk[0][1]);
                    accH[g*2][0] += t[0]; accH[g*2][1] += t[1];
                    accH[g*2][2] += t[2]; accH[g*2][3] += t[3];
                    mma16816_z(t, aq[0], bk[0][2], bk[0][3]);
                    accH[g*2+1][0] += t[0]; accH[g*2+1][1] += t[1];
                    accH[g*2+1][2] += t[2]; accH[g*2+1][3] += t[3];
                }
                // corrections
#pragma unroll
                for (int p = 0; p < 5; p++) {
                    mma16816(accL[g*2],   aq[pa[p]], bk[pb[p]][0], bk[pb[p]][1]);
                    mma16816(accL[g*2+1], aq[pa[p]], bk[pb[p]][2], bk[pb[p]][3]);
                }
            }
        }

        // ---- floor(S/8), online softmax ----
        float S[8][4];
        float mt0 = -1e30f, mt1 = -1e30f;
#pragma unroll
        for (int ni = 0; ni < 8; ni++) {
            S[ni][0] = floorf((accH[ni][0] + accL[ni][0]) * 0.125f);
            S[ni][1] = floorf((accH[ni][1] + accL[ni][1]) * 0.125f);
            S[ni][2] = floorf((accH[ni][2] + accL[ni][2]) * 0.125f);
            S[ni][3] = floorf((accH[ni][3] + accL[ni][3]) * 0.125f);
            mt0 = fmaxf(mt0, fmaxf(S[ni][0], S[ni][1]));
            mt1 = fmaxf(mt1, fmaxf(S[ni][2], S[ni][3]));
        }
#pragma unroll
        for (int off = 1; off <= 2; off <<= 1) {
            mt0 = fmaxf(mt0, __shfl_xor_sync(0xffffffffu, mt0, off));
            mt1 = fmaxf(mt1, __shfl_xor_sync(0xffffffffu, mt1, off));
        }
        const float mn0 = fmaxf(m0, mt0), mn1 = fmaxf(m1, mt1);
        const float sc0 = __expf(m0 - mn0), sc1 = __expf(m1 - mn1);
        m0 = mn0; m1 = mn1;

        float rs0 = 0.0f, rs1 = 0.0f;
#pragma unroll
        for (int ni = 0; ni < 8; ni++) {
            S[ni][0] = __expf(S[ni][0] - mn0);
            S[ni][1] = __expf(S[ni][1] - mn0);
            S[ni][2] = __expf(S[ni][2] - mn1);
            S[ni][3] = __expf(S[ni][3] - mn1);
            rs0 += S[ni][0] + S[ni][1];
            rs1 += S[ni][2] + S[ni][3];
        }
#pragma unroll
        for (int off = 1; off <= 2; off <<= 1) {
            rs0 += __shfl_xor_sync(0xffffffffu, rs0, off);
            rs1 += __shfl_xor_sync(0xffffffffu, rs1, off);
        }
        ls0 = ls0 * sc0 + rs0;
        ls1 = ls1 * sc1 + rs1;
#pragma unroll
        for (int ni = 0; ni < 8; ni++) {
            oH[ni][0] *= sc0; oH[ni][1] *= sc0;
            oH[ni][2] *= sc1; oH[ni][3] *= sc1;
        }

        // ---- P -> 2 bf16 planes (warp-private smem rows) ----
#pragma unroll
        for (int ni = 0; ni < 8; ni++) {
            uint16_t p00, p01, p10, p11, q00, q01, q10, q11;
            split2(S[ni][0], p00, q00);
            split2(S[ni][1], p01, q01);
            split2(S[ni][2], p10, q10);
            split2(S[ni][3], p11, q11);
            const uint32_t clo = sw128(pst_lo + ni * 16);
            const uint32_t chi = sw128(pst_hi + ni * 16);
            *(uint32_t*)(smem + AP_OFF + clo) = (uint32_t)p00 | ((uint32_t)p01 << 16);
            *(uint32_t*)(smem + AP_OFF + chi) = (uint32_t)p10 | ((uint32_t)p11 << 16);
            *(uint32_t*)(smem + AP_OFF + 16384 + clo) = (uint32_t)q00 | ((uint32_t)q01 << 16);
            *(uint32_t*)(smem + AP_OFF + 16384 + chi) = (uint32_t)q10 | ((uint32_t)q11 << 16);
        }
        __syncwarp();

        // ---- O += P V (bf16x3 emulated) ----
        float accP[8][4];
#pragma unroll
        for (int ni = 0; ni < 8; ni++)
#pragma unroll
            for (int c = 0; c < 4; c++) accP[ni][c] = 0.0f;

        const uint32_t Ps = sb + AP_OFF;
#pragma unroll
        for (int ks = 0; ks < 4; ks++) {
            const uint32_t kx = (uint32_t)(ks << 5);
            uint32_t ap0[4], ap1[4];
            ldsm4(ap0, Ps + (offA ^ kx));
            ldsm4(ap1, Ps + 16384 + (offA ^ kx));
#pragma unroll
            for (int g = 0; g < 4; g++) {
                uint32_t bv0[4], bv1[4];
                ldsm4(bv0, Vs + (offB[g] ^ kx));
                ldsm4(bv1, Vs + 8192 + (offB[g] ^ kx));
                {
                    float t[4];
                    mma16816_z(t, ap0, bv0[0], bv0[1]);
                    oH[g*2][0] += t[0]; oH[g*2][1] += t[1];
                    oH[g*2][2] += t[2]; oH[g*2][3] += t[3];
                    mma16816_z(t, ap0, bv0[2], bv0[3]);
                    oH[g*2+1][0] += t[0]; oH[g*2+1][1] += t[1];
                    oH[g*2+1][2] += t[2]; oH[g*2+1][3] += t[3];
                }
                mma16816(accP[g*2],   ap1, bv0[0], bv0[1]);
                mma16816(accP[g*2+1], ap1, bv0[2], bv0[3]);
                mma16816(accP[g*2],   ap0, bv1[0], bv1[1]);
                mma16816(accP[g*2+1], ap0, bv1[2], bv1[3]);
            }
        }
#pragma unroll
        for (int ni = 0; ni < 8; ni++)
#pragma unroll
            for (int c = 0; c < 4; c++) oH[ni][c] += accP[ni][c];

        __syncthreads();  // stage reuse barrier (K/V of this kt consumed)
    }

    // ---- epilogue ----
    const float inv0 = 1.0f / ls0;
    const float inv1 = 1.0f / ls1;
    const int r0 = q0 + prlo;
#pragma unroll
    for (int ni = 0; ni < 8; ni++) {
        const int cb = hofs + ni * 8 + 2 * (l & 3);
        *(float2*)(Out + (rowbase + r0) * EE + cb) =
            make_float2(oH[ni][0] * inv0, oH[ni][1] * inv0);
        *(float2*)(Out + (rowbase + r0 + 8) * EE + cb) =
            make_float2(oH[ni][2] * inv1, oH[ni][3] * inv1);
    }
}

// ---------------------------------------------------------------------------
extern "C" void kernel_launch(void* const* d_in, const int* in_sizes, int n_in,
                              void* d_out, int out_size)
{
    const float* key   = (const float*)d_in[0];
    const float* query = (const float*)d_in[1];
    const float* value = (const float*)d_in[2];
    const float* Wq    = (const float*)d_in[3];
    const float* bq    = (const float*)d_in[4];
    const float* Wk    = (const float*)d_in[5];
    const float* bk    = (const float*)d_in[6];
    const float* Wv    = (const float*)d_in[7];
    const float* bv    = (const float*)d_in[8];
    float* out = (float*)d_out;

    void *pq = 0, *pk = 0, *pv = 0;
    cudaGetSymbolAddress(&pq, g_q);
    cudaGetSymbolAddress(&pk, g_k);
    cudaGetSymbolAddress(&pv, g_v);

    cudaFuncSetAttribute(proj_mma, cudaFuncAttributeMaxDynamicSharedMemorySize,
                         PROJ_SMEM);
    cudaFuncSetAttribute(attn_mma, cudaFuncAttributeMaxDynamicSharedMemorySize,
                         ATTN_SMEM);

    dim3 sgrid(MM * EE / 1024, 3);
    split_act<<<sgrid, 256>>>(query, key, value);
    dim3 wgrid(EE * EE / 1024, 3);
    split_w<<<wgrid, 256>>>(Wq, Wk, Wv);

    dim3 pgrid(EE / 128, MM / 128, 3);
    proj_mma<<<pgrid, 256, PROJ_SMEM>>>(bq, bk, bv,
                                        (float*)pq, (float*)pk, (float*)pv);

    dim3 qkgrid(MM * EE / 1024, 2);
    split_qk<<<qkgrid, 256>>>();
    dim3 vtgrid(SS / 64, BB * HH);
    split_vt<<<vtgrid, 256>>>();

    dim3 agrid(SS / 128, HH, BB);
    attn_mma<<<agrid, 256, ATTN_SMEM>>>(out);
}

// round 8
// speedup vs baseline: 1.0765x; 1.0750x over previous
#include <cuda_runtime.h>
#include <math.h>
#include <stdint.h>

#define BB 4
#define SS 2048
#define EE 1024
#define HH 16
#define DD 64
#define MM (BB*SS)

typedef unsigned long long u64;

// Projected q, k, v: [B*S, E] row-major (col = h*64 + d)
__device__ float g_q[MM * EE];
__device__ float g_k[MM * EE];
__device__ float g_v[MM * EE];

// ---------------------------------------------------------------------------
// packed f32x2 helpers (Blackwell)
// ---------------------------------------------------------------------------
__device__ __forceinline__ void fma2(u64& c, u64 a, u64 b) {
    asm("fma.rn.f32x2 %0, %1, %2, %0;" : "+l"(c) : "l"(a), "l"(b));
}
__device__ __forceinline__ u64 mul2(u64 a, u64 b) {
    u64 c;
    asm("mul.rn.f32x2 %0, %1, %2;" : "=l"(c) : "l"(a), "l"(b));
    return c;
}
__device__ __forceinline__ u64 pack2(float l, float h) {
    u64 o;
    asm("mov.b64 %0, {%1, %2};" : "=l"(o) : "f"(l), "f"(h));
    return o;
}
__device__ __forceinline__ u64 dup2(float x) {
    u64 o;
    asm("mov.b64 %0, {%1, %1};" : "=l"(o) : "f"(x));
    return o;
}
__device__ __forceinline__ void unpack2(float& l, float& h, u64 u) {
    asm("mov.b64 {%0, %1}, %2;" : "=f"(l), "=f"(h) : "l"(u));
}

// ===========================================================================
// Projection GEMM, f32x2: C[m,n] = sum_k A[m,k]*W[n,k] + bias[n]
// 128x128 tile, BK=8, 256 threads. Pairs along n. Ws natural (pad 132);
// AsD holds each A value duplicated {a,a} (pad 258) so the m-operand b64
// load is a 2-address broadcast. Thread (tx,ty): m = ty+16s (s=0..7),
// n-pairs 2tx+32t (t=0..3). Per-element k-order identical to scalar R1.
// ===========================================================================
__global__ __launch_bounds__(256, 2)
void proj_gemm2(const float* __restrict__ A, const float* __restrict__ W,
                const float* __restrict__ bias, float* __restrict__ C)
{
    __shared__ float AsD[8 * 258];
    __shared__ float Ws[8 * 132];
    const int K = EE;
    const int bm = blockIdx.y * 128;
    const int bn = blockIdx.x * 128;
    const int tid = threadIdx.x;
    const int tx = tid & 15;
    const int ty = tid >> 4;
    const int lrow = tid >> 1;
    const int lk = (tid & 1) * 4;

    const float* Ap = A + (size_t)(bm + lrow) * K + lk;
    const float* Wp = W + (size_t)(bn + lrow) * K + lk;

    u64 acc2[8][4];
#pragma unroll
    for (int s = 0; s < 8; s++)
#pragma unroll
        for (int t = 0; t < 4; t++) acc2[s][t] = 0ULL;

    float4 a4 = *(const float4*)(Ap);
    float4 w4 = *(const float4*)(Wp);

    const int awb = 32 * (lrow >> 4) + 2 * (lrow & 15);

    for (int k0 = 0; k0 < K; k0 += 8) {
        *(float2*)&AsD[(lk + 0) * 258 + awb] = make_float2(a4.x, a4.x);
        *(float2*)&AsD[(lk + 1) * 258 + awb] = make_float2(a4.y, a4.y);
        *(float2*)&AsD[(lk + 2) * 258 + awb] = make_float2(a4.z, a4.z);
        *(float2*)&AsD[(lk + 3) * 258 + awb] = make_float2(a4.w, a4.w);
        Ws[(lk + 0) * 132 + lrow] = w4.x;
        Ws[(lk + 1) * 132 + lrow] = w4.y;
        Ws[(lk + 2) * 132 + lrow] = w4.z;
        Ws[(lk + 3) * 132 + lrow] = w4.w;
        __syncthreads();

        if (k0 + 8 < K) {
            a4 = *(const float4*)(Ap + k0 + 8);
            w4 = *(const float4*)(Wp + k0 + 8);
        }

#pragma unroll
        for (int kk = 0; kk < 8; kk++) {
            u64 ad[8], wp[4];
#pragma unroll
            for (int s = 0; s < 8; s++)
                ad[s] = *(const u64*)(AsD + kk * 258 + 32 * s + 2 * ty);
#pragma unroll
            for (int t = 0; t < 4; t++)
                wp[t] = *(const u64*)(Ws + kk * 132 + 2 * tx + 32 * t);
#pragma unroll
            for (int s = 0; s < 8; s++)
#pragma unroll
                for (int t = 0; t < 4; t++)
                    fma2(acc2[s][t], ad[s], wp[t]);
        }
        __syncthreads();
    }

#pragma unroll
    for (int s = 0; s < 8; s++) {
        const int m = bm + ty + 16 * s;
#pragma unroll
        for (int t = 0; t < 4; t++) {
            const int n = bn + 2 * tx + 32 * t;
            float lo, hi;
            unpack2(lo, hi, acc2[s][t]);
            *(float2*)(C + (size_t)m * EE + n) =
                make_float2(lo + bias[n], hi + bias[n + 1]);
        }
    }
}

// ===========================================================================
// Flash attention, f32x2. Identical structure/layouts/order to R1 scalar
// (bitwise-equal output): S-tile pairs along k (adjacent k contiguous in the
// swizzled d-major K tile -> u64 pairs come free from the 16B loads; q
// duplicated per-register). PV pairs along q (adjacent q contiguous in Pt;
// v duplicated per-register).
// ===========================================================================
__global__ __launch_bounds__(256, 1)
void attn2(float* __restrict__ Out)
{
    extern __shared__ float sm[];
    float* Qs = sm;                 // 64*128, d-major swizzled
    float* Ks = Qs + 64 * 128;      // 64*128, d-major swizzled
    float* Vs = Ks + 64 * 128;      // 128*64, natural
    float* Pt = Vs + 128 * 64;      // 128*128, c-major swizzled
    float4* Qs4 = (float4*)Qs;
    float4* Pt4 = (float4*)Pt;
    const ulonglong2* Ks16 = (const ulonglong2*)Ks;
    const ulonglong2* Pt16 = (const ulonglong2*)Pt;

    const int b = blockIdx.z;
    const int h = blockIdx.y;
    const int q0 = blockIdx.x * 128;
    const int tid = threadIdx.x;
    const int g = tid & 15;
    const int w = tid >> 4;
    const size_t base = (size_t)b * SS * EE + (size_t)h * DD;

    // Load Q tile transposed (d-major) with XOR swizzle on r-blocks.
    for (int t = tid; t < 128 * 16; t += 256) {
        const int r  = t >> 4;
        const int d4 = (t & 15) << 2;
        const float4 v = *(const float4*)(g_q + base + (size_t)(q0 + r) * EE + d4);
        const int r4 = r >> 2, rm = r & 3;
        const int sd = (d4 >> 3) & 7;
        Qs[((d4 + 0) << 7) + ((r4 ^ sd) << 2) + rm] = v.x;
        Qs[((d4 + 1) << 7) + ((r4 ^ sd) << 2) + rm] = v.y;
        Qs[((d4 + 2) << 7) + ((r4 ^ sd) << 2) + rm] = v.z;
        Qs[((d4 + 3) << 7) + ((r4 ^ sd) << 2) + rm] = v.w;
    }

    float mrow[8], lrs[8];
    u64 o2[4][4];                   // q-row pairs x 4 d-cols
#pragma unroll
    for (int j = 0; j < 8; j++) { mrow[j] = -1e30f; lrs[j] = 0.0f; }
#pragma unroll
    for (int j2 = 0; j2 < 4; j2++)
#pragma unroll
        for (int dd = 0; dd < 4; dd++) o2[j2][dd] = 0ULL;

    for (int kt = 0; kt < SS; kt += 128) {
        __syncthreads();

        // Load K (transposed+swizzled) and V (natural) tiles
        for (int t = tid; t < 128 * 16; t += 256) {
            const int r  = t >> 4;
            const int d4 = (t & 15) << 2;
            const size_t goff = base + (size_t)(kt + r) * EE + d4;
            const float4 kv = *(const float4*)(g_k + goff);
            const int r4 = r >> 2, rm = r & 3;
            const int sd = (d4 >> 3) & 7;
            Ks[((d4 + 0) << 7) + ((r4 ^ sd) << 2) + rm] = kv.x;
            Ks[((d4 + 1) << 7) + ((r4 ^ sd) << 2) + rm] = kv.y;
            Ks[((d4 + 2) << 7) + ((r4 ^ sd) << 2) + rm] = kv.z;
            Ks[((d4 + 3) << 7) + ((r4 ^ sd) << 2) + rm] = kv.w;
            const float4 vv = *(const float4*)(g_v + goff);
            *(float4*)&Vs[(r << 6) + d4] = vv;
        }
        __syncthreads();

        // ---- S^T tile: acc2[i2][j], pair i2 = k-cols (8g+2i2, +1), row j ----
        u64 acc2[4][8];
#pragma unroll
        for (int i2 = 0; i2 < 4; i2++)
#pragma unroll
            for (int j = 0; j < 8; j++) acc2[i2][j] = 0ULL;

#pragma unroll 8
        for (int d = 0; d < 64; d++) {
            const int sd = (d >> 3) & 7;
            const ulonglong2 ka = Ks16[(d << 5) + ((g * 2) ^ sd)];
            const ulonglong2 kb = Ks16[(d << 5) + ((g * 2 + 1) ^ sd)];
            const float4 qa = Qs4[(d << 5) + ((w * 2) ^ sd)];
            const float4 qb = Qs4[(d << 5) + ((w * 2 + 1) ^ sd)];
            const u64 kp[4] = {ka.x, ka.y, kb.x, kb.y};
            const u64 qd[8] = {dup2(qa.x), dup2(qa.y), dup2(qa.z), dup2(qa.w),
                               dup2(qb.x), dup2(qb.y), dup2(qb.z), dup2(qb.w)};
#pragma unroll
            for (int i2 = 0; i2 < 4; i2++)
#pragma unroll
                for (int j = 0; j < 8; j++)
                    fma2(acc2[i2][j], kp[i2], qd[j]);
        }

        // Unpack (register aliasing) to Sf[i][j], i = k-col offset 0..7
        float Sf[8][8];
#pragma unroll
        for (int i2 = 0; i2 < 4; i2++)
#pragma unroll
            for (int j = 0; j < 8; j++)
                unpack2(Sf[2 * i2][j], Sf[2 * i2 + 1][j], acc2[i2][j]);

        // scores = floor(dot / 8)
#pragma unroll
        for (int i = 0; i < 8; i++)
#pragma unroll
            for (int j = 0; j < 8; j++)
                Sf[i][j] = floorf(Sf[i][j] * 0.125f);

        // Row max over the 128 k-cols of each q-row
        float mt[8];
#pragma unroll
        for (int j = 0; j < 8; j++) {
            float m = Sf[0][j];
#pragma unroll
            for (int i = 1; i < 8; i++) m = fmaxf(m, Sf[i][j]);
            mt[j] = m;
        }
#pragma unroll
        for (int off = 8; off >= 1; off >>= 1)
#pragma unroll
            for (int j = 0; j < 8; j++)
                mt[j] = fmaxf(mt[j], __shfl_xor_sync(0xffffffffu, mt[j], off));

        float scj[8], rs[8];
#pragma unroll
        for (int j = 0; j < 8; j++) {
            const float mn = fmaxf(mrow[j], mt[j]);
            scj[j] = __expf(mrow[j] - mn);   // 0 on first tile
            mrow[j] = mn;
            float s = 0.0f;
#pragma unroll
            for (int i = 0; i < 8; i++) {
                Sf[i][j] = __expf(Sf[i][j] - mn);
                s += Sf[i][j];
            }
            rs[j] = s;
        }
#pragma unroll
        for (int off = 8; off >= 1; off >>= 1)
#pragma unroll
            for (int j = 0; j < 8; j++)
                rs[j] += __shfl_xor_sync(0xffffffffu, rs[j], off);
#pragma unroll
        for (int j = 0; j < 8; j++)
            lrs[j] = lrs[j] * scj[j] + rs[j];
#pragma unroll
        for (int j2 = 0; j2 < 4; j2++) {
            const u64 sc2 = pack2(scj[2 * j2], scj[2 * j2 + 1]);
#pragma unroll
            for (int dd = 0; dd < 4; dd++)
                o2[j2][dd] = mul2(o2[j2][dd], sc2);
        }

        // Store P^T (c-major, q float4-contiguous, swizzled)
#pragma unroll
        for (int i = 0; i < 8; i++) {
            const int c = g * 8 + i;
            const int sw = g & 7;   // (c>>3)&7
            Pt4[(c << 5) + ((w * 2) ^ sw)] =
                make_float4(Sf[i][0], Sf[i][1], Sf[i][2], Sf[i][3]);
            Pt4[(c << 5) + ((w * 2 + 1) ^ sw)] =
                make_float4(Sf[i][4], Sf[i][5], Sf[i][6], Sf[i][7]);
        }
        __syncthreads();

        // O += P V; pairs along q: o2[j2][dd], rows (8w+2j2, +1), d = 4g+dd
#pragma unroll 8
        for (int k = 0; k < 128; k++) {
            const int sw = (k >> 3) & 7;
            const ulonglong2 pA = Pt16[(k << 5) + ((w * 2) ^ sw)];
            const ulonglong2 pB = Pt16[(k << 5) + ((w * 2 + 1) ^ sw)];
            const float4 vv = *(const float4*)&Vs[(k << 6) + (g << 2)];
            const u64 pp[4] = {pA.x, pA.y, pB.x, pB.y};
            const u64 vd[4] = {dup2(vv.x), dup2(vv.y), dup2(vv.z), dup2(vv.w)};
#pragma unroll
            for (int j2 = 0; j2 < 4; j2++)
#pragma unroll
                for (int dd = 0; dd < 4; dd++)
                    fma2(o2[j2][dd], pp[j2], vd[dd]);
        }
    }

    // Epilogue: normalize and store. Out col = h*64 + g*4 + dd
#pragma unroll
    for (int j = 0; j < 8; j++) {
        const int j2 = j >> 1;
        const float inv = 1.0f / lrs[j];
        float o[4];
#pragma unroll
        for (int dd = 0; dd < 4; dd++) {
            float lo, hi;
            unpack2(lo, hi, o2[j2][dd]);
            o[dd] = (j & 1) ? hi : lo;
        }
        const int r = q0 + w * 8 + j;
        *(float4*)(Out + base + (size_t)r * EE + (g << 2)) =
            make_float4(o[0] * inv, o[1] * inv, o[2] * inv, o[3] * inv);
    }
}

// ---------------------------------------------------------------------------
extern "C" void kernel_launch(void* const* d_in, const int* in_sizes, int n_in,
                              void* d_out, int out_size)
{
    const float* key   = (const float*)d_in[0];
    const float* query = (const float*)d_in[1];
    const float* value = (const float*)d_in[2];
    const float* Wq    = (const float*)d_in[3];
    const float* bq    = (const float*)d_in[4];
    const float* Wk    = (const float*)d_in[5];
    const float* bk    = (const float*)d_in[6];
    const float* Wv    = (const float*)d_in[7];
    const float* bv    = (const float*)d_in[8];
    float* out = (float*)d_out;

    void *pq = 0, *pk = 0, *pv = 0;
    cudaGetSymbolAddress(&pq, g_q);
    cudaGetSymbolAddress(&pk, g_k);
    cudaGetSymbolAddress(&pv, g_v);

    const int ATTN_SMEM = (64 * 128 + 64 * 128 + 128 * 64 + 128 * 128) * 4; // 160 KB
    cudaFuncSetAttribute(attn2, cudaFuncAttributeMaxDynamicSharedMemorySize,
                         ATTN_SMEM);

    dim3 pgrid(EE / 128, MM / 128);
    proj_gemm2<<<pgrid, 256>>>(query, Wq, bq, (float*)pq);
    proj_gemm2<<<pgrid, 256>>>(key,   Wk, bk, (float*)pk);
    proj_gemm2<<<pgrid, 256>>>(value, Wv, bv, (float*)pv);

    dim3 agrid(SS / 128, HH, BB);
    attn2<<<agrid, 256, ATTN_SMEM>>>(out);
}

// round 11
// speedup vs baseline: 1.1962x; 1.1112x over previous
#include <cuda_runtime.h>
#include <cuda_bf16.h>
#include <math.h>
#include <stdint.h>

#define BB 4
#define SS 2048
#define EE 1024
#define HH 16
#define DD 64
#define MM (BB*SS)

typedef unsigned long long u64;

// Projected q, k, v fp32: [B*S, E] row-major (col = h*64 + d)
__device__ float g_q[MM * EE];
__device__ float g_k[MM * EE];
__device__ float g_v[MM * EE];

// bf16 split planes of inputs (for proj GEMMs)
__device__ uint16_t g_sa[3][3][MM * EE];
__device__ uint16_t g_sw[3][3][EE * EE];

// ===========================================================================
// helpers
// ===========================================================================
__device__ __forceinline__ uint32_t smem_u32(const void* p) {
    uint32_t a;
    asm("{ .reg .u64 t; cvta.to.shared.u64 t, %1; cvt.u32.u64 %0, t; }"
        : "=r"(a) : "l"(p));
    return a;
}
__device__ __forceinline__ uint32_t sw128(uint32_t off) {
    return off ^ ((off >> 3) & 0x70);
}
__device__ __forceinline__ void split3(float x, uint16_t& b0, uint16_t& b1, uint16_t& b2) {
    __nv_bfloat16 h0 = __float2bfloat16_rn(x);
    float r = x - __bfloat162float(h0);
    __nv_bfloat16 h1 = __float2bfloat16_rn(r);
    r -= __bfloat162float(h1);
    __nv_bfloat16 h2 = __float2bfloat16_rn(r);
    b0 = __bfloat16_as_ushort(h0);
    b1 = __bfloat16_as_ushort(h1);
    b2 = __bfloat16_as_ushort(h2);
}
__device__ __forceinline__ void ldsm4(uint32_t* r, uint32_t addr) {
    asm volatile("ldmatrix.sync.aligned.m8n8.x4.shared.b16 {%0,%1,%2,%3}, [%4];"
        : "=r"(r[0]), "=r"(r[1]), "=r"(r[2]), "=r"(r[3]) : "r"(addr));
}
// chained accumulate (correction chains only — small magnitude)
__device__ __forceinline__ void mma16816(float* c, const uint32_t* a,
                                         uint32_t b0, uint32_t b1) {
    asm volatile("mma.sync.aligned.m16n8k16.row.col.f32.bf16.bf16.f32 "
        "{%0,%1,%2,%3}, {%4,%5,%6,%7}, {%8,%9}, {%0,%1,%2,%3};"
        : "+f"(c[0]), "+f"(c[1]), "+f"(c[2]), "+f"(c[3])
        : "r"(a[0]), "r"(a[1]), "r"(a[2]), "r"(a[3]), "r"(b0), "r"(b1));
}
// Zero-C variant: d = A*B (k16 partial only) — main chain uses this + FADD drain
__device__ __forceinline__ void mma16816_z(float* d, const uint32_t* a,
                                           uint32_t b0, uint32_t b1) {
    asm volatile("mma.sync.aligned.m16n8k16.row.col.f32.bf16.bf16.f32 "
        "{%0,%1,%2,%3}, {%4,%5,%6,%7}, {%8,%9}, {%10,%11,%12,%13};"
        : "=f"(d[0]), "=f"(d[1]), "=f"(d[2]), "=f"(d[3])
        : "r"(a[0]), "r"(a[1]), "r"(a[2]), "r"(a[3]), "r"(b0), "r"(b1),
          "f"(0.0f), "f"(0.0f), "f"(0.0f), "f"(0.0f));
}
// packed f32x2
__device__ __forceinline__ void fma2(u64& c, u64 a, u64 b) {
    asm("fma.rn.f32x2 %0, %1, %2, %0;" : "+l"(c) : "l"(a), "l"(b));
}
__device__ __forceinline__ u64 mul2(u64 a, u64 b) {
    u64 c;
    asm("mul.rn.f32x2 %0, %1, %2;" : "=l"(c) : "l"(a), "l"(b));
    return c;
}
__device__ __forceinline__ u64 pack2(float l, float h) {
    u64 o;
    asm("mov.b64 %0, {%1, %2};" : "=l"(o) : "f"(l), "f"(h));
    return o;
}
__device__ __forceinline__ u64 dup2(float x) {
    u64 o;
    asm("mov.b64 %0, {%1, %1};" : "=l"(o) : "f"(x));
    return o;
}
__device__ __forceinline__ void unpack2(float& l, float& h, u64 u) {
    asm("mov.b64 {%0, %1}, %2;" : "=f"(l), "=f"(h) : "l"(u));
}
#define CPASYNC16(s, g) \
    asm volatile("cp.async.cg.shared.global [%0], [%1], 16;" :: "r"(s), "l"(g))
#define CP_COMMIT() asm volatile("cp.async.commit_group;" ::: "memory")
#define CP_WAIT1()  asm volatile("cp.async.wait_group 1;" ::: "memory")
#define CP_WAIT0()  asm volatile("cp.async.wait_group 0;" ::: "memory")

// ===========================================================================
// Split conversion kernels (inputs only)
// ===========================================================================
__global__ __launch_bounds__(256)
void split_act(const float* __restrict__ q, const float* __restrict__ k,
               const float* __restrict__ v)
{
    const int z = blockIdx.y;
    const float* src = (z == 0) ? q : (z == 1) ? k : v;
    const size_t i = ((size_t)blockIdx.x * 256 + threadIdx.x) * 4;
    const float4 x = *(const float4*)(src + i);
    uint16_t b0[4], b1[4], b2[4];
    split3(x.x, b0[0], b1[0], b2[0]);
    split3(x.y, b0[1], b1[1], b2[1]);
    split3(x.z, b0[2], b1[2], b2[2]);
    split3(x.w, b0[3], b1[3], b2[3]);
    *(ushort4*)&g_sa[z][0][i] = make_ushort4(b0[0], b0[1], b0[2], b0[3]);
    *(ushort4*)&g_sa[z][1][i] = make_ushort4(b1[0], b1[1], b1[2], b1[3]);
    *(ushort4*)&g_sa[z][2][i] = make_ushort4(b2[0], b2[1], b2[2], b2[3]);
}

__global__ __launch_bounds__(256)
void split_w(const float* __restrict__ wq, const float* __restrict__ wk,
             const float* __restrict__ wv)
{
    const int z = blockIdx.y;
    const float* src = (z == 0) ? wq : (z == 1) ? wk : wv;
    const size_t i = ((size_t)blockIdx.x * 256 + threadIdx.x) * 4;
    const float4 x = *(const float4*)(src + i);
    uint16_t b0[4], b1[4], b2[4];
    split3(x.x, b0[0], b1[0], b2[0]);
    split3(x.y, b0[1], b1[1], b2[1]);
    split3(x.z, b0[2], b1[2], b2[2]);
    split3(x.w, b0[3], b1[3], b2[3]);
    *(ushort4*)&g_sw[z][0][i] = make_ushort4(b0[0], b0[1], b0[2], b0[3]);
    *(ushort4*)&g_sw[z][1][i] = make_ushort4(b1[0], b1[1], b1[2], b1[3]);
    *(ushort4*)&g_sw[z][2][i] = make_ushort4(b2[0], b2[1], b2[2], b2[3]);
}

// ===========================================================================
// Projection GEMM via mma.sync, bf16-split, R5 structure (VALIDATED):
// main chain (0,0) issued with C=0 and drained into accH via fp32 RN FADD
// (chained HMMA accumulate is NOT clean RN — R10 proved it);
// correction chains -> accL (chained; magnitude ~2^-9 so chop is harmless).
// Q/K: 5 corrections. V: 2 corrections (V errors bypass the floor).
// ===========================================================================
#define TILE_B   16384
#define STAGE_B  (6 * TILE_B)
#define PROJ_SMEM (2 * STAGE_B)
#define KT_STEPS 16

__global__ __launch_bounds__(256, 1)
void proj_mma(const float* __restrict__ bq, const float* __restrict__ bk,
              const float* __restrict__ bv,
              float* __restrict__ Cq, float* __restrict__ Ck,
              float* __restrict__ Cv)
{
    extern __shared__ char smem[];
    const uint32_t sb = smem_u32(smem);
    const int tid = threadIdx.x;
    const int wid = tid >> 5;
    const int l   = tid & 31;
    const int wm = wid >> 2;
    const int wn = wid & 3;

    const int z  = blockIdx.z;
    const int bn = blockIdx.x * 128;
    const int bm = blockIdx.y * 128;
    const float* bias = (z == 0) ? bq : (z == 1) ? bk : bv;
    float*       C    = (z == 0) ? Cq : (z == 1) ? Ck : Cv;
    const int ncorr = (z == 2) ? 2 : 5;

    uint32_t swA[4], swB[2];
#pragma unroll
    for (int mi = 0; mi < 4; mi++)
        swA[mi] = sw128((uint32_t)((wm * 64 + mi * 16 + (l & 15)) * 128
                                   + ((l >> 4) << 4)));
#pragma unroll
    for (int nh = 0; nh < 2; nh++)
        swB[nh] = sw128((uint32_t)((wn * 32 + nh * 16 + ((l >> 4) & 1) * 8
                                    + (l & 7)) * 128 + (((l >> 3) & 1) << 4)));

    float accH[4][4][4];
    float accL[4][4][4];
#pragma unroll
    for (int mi = 0; mi < 4; mi++)
#pragma unroll
        for (int ni = 0; ni < 4; ni++)
#pragma unroll
            for (int c = 0; c < 4; c++) {
                accH[mi][ni][c] = 0.0f;
                accL[mi][ni][c] = 0.0f;
            }

    auto load_stage = [&](int kt, int st) {
        const uint32_t stage = sb + st * STAGE_B;
#pragma unroll
        for (int i = 0; i < 24; i++) {
            const int idx = tid + i * 256;
            const int plane = idx >> 10;
            const int chunk = idx & 1023;
            const int r = chunk >> 3;
            const int c = chunk & 7;
            const uint16_t* gp = (plane < 3)
                ? &g_sa[z][plane][(size_t)(bm + r) * EE + kt * 64 + c * 8]
                : &g_sw[z][plane - 3][(size_t)(bn + r) * EE + kt * 64 + c * 8];
            const uint32_t s = stage + plane * TILE_B + sw128((uint32_t)(r * 128 + c * 16));
            CPASYNC16(s, gp);
        }
        CP_COMMIT();
    };

    load_stage(0, 0);

    const int pa[5] = {1, 0, 2, 1, 0};
    const int pb[5] = {0, 1, 0, 1, 2};

    for (int kt = 0; kt < KT_STEPS; kt++) {
        if (kt + 1 < KT_STEPS) {
            load_stage(kt + 1, (kt + 1) & 1);
            CP_WAIT1();
        } else {
            CP_WAIT0();
        }
        __syncthreads();

        const uint32_t As = sb + (kt & 1) * STAGE_B;
        const uint32_t Bs = As + 3 * TILE_B;

        // ---- main chain (0,0): C=0 HMMA + fp32 RN drain ----
#pragma unroll
        for (int ks = 0; ks < 4; ks++) {
            const uint32_t kx = (uint32_t)(ks << 5);
            uint32_t a[4][4], b[2][4];
#pragma unroll
            for (int mi = 0; mi < 4; mi++)
                ldsm4(a[mi], As + (swA[mi] ^ kx));
#pragma unroll
            for (int nh = 0; nh < 2; nh++)
                ldsm4(b[nh], Bs + (swB[nh] ^ kx));
#pragma unroll
            for (int mi = 0; mi < 4; mi++) {
#pragma unroll
                for (int ni = 0; ni < 4; ni++) {
                    float t[4];
                    const uint32_t bb0 = b[ni >> 1][(ni & 1) * 2];
                    const uint32_t bb1 = b[ni >> 1][(ni & 1) * 2 + 1];
                    mma16816_z(t, a[mi], bb0, bb1);
                    accH[mi][ni][0] += t[0];
                    accH[mi][ni][1] += t[1];
                    accH[mi][ni][2] += t[2];
                    accH[mi][ni][3] += t[3];
                }
            }
        }

        // ---- correction chains -> accL (chained) ----
        for (int p = 0; p < ncorr; p++) {
            const uint32_t at = As + pa[p] * TILE_B;
            const uint32_t bt = Bs + pb[p] * TILE_B;
#pragma unroll
            for (int ks = 0; ks < 4; ks++) {
                const uint32_t kx = (uint32_t)(ks << 5);
                uint32_t a[4][4], b[2][4];
#pragma unroll
                for (int mi = 0; mi < 4; mi++)
                    ldsm4(a[mi], at + (swA[mi] ^ kx));
#pragma unroll
                for (int nh = 0; nh < 2; nh++)
                    ldsm4(b[nh], bt + (swB[nh] ^ kx));
#pragma unroll
                for (int mi = 0; mi < 4; mi++) {
                    mma16816(accL[mi][0], a[mi], b[0][0], b[0][1]);
                    mma16816(accL[mi][1], a[mi], b[0][2], b[0][3]);
                    mma16816(accL[mi][2], a[mi], b[1][0], b[1][1]);
                    mma16816(accL[mi][3], a[mi], b[1][2], b[1][3]);
                }
            }
        }
        __syncthreads();
    }

#pragma unroll
    for (int mi = 0; mi < 4; mi++) {
        const int r0 = bm + wm * 64 + mi * 16 + (l >> 2);
#pragma unroll
        for (int ni = 0; ni < 4; ni++) {
            const int cb = bn + wn * 32 + ni * 8 + 2 * (l & 3);
            const float bx = bias[cb], by = bias[cb + 1];
            float2 v0 = make_float2(accH[mi][ni][0] + accL[mi][ni][0] + bx,
                                    accH[mi][ni][1] + accL[mi][ni][1] + by);
            float2 v1 = make_float2(accH[mi][ni][2] + accL[mi][ni][2] + bx,
                                    accH[mi][ni][3] + accL[mi][ni][3] + by);
            *(float2*)(C + (size_t)r0 * EE + cb) = v0;
            *(float2*)(C + (size_t)(r0 + 8) * EE + cb) = v1;
        }
    }
}

// ===========================================================================
// Flash attention, f32x2, 512 threads (16 warps, 4/SMSP) for latency hiding.
// Same per-element accumulation/reduction order as R8 (bitwise R1-class).
// S phase: thread (g=tid&15, w=tid>>4) owns k-cols g*8..+7, q-rows w*4..+3.
// PV phase: rows w*4..+3, d-cols g*4..+3.
// ===========================================================================
__global__ __launch_bounds__(512, 1)
void attn2(float* __restrict__ Out)
{
    extern __shared__ float sm[];
    float* Qs = sm;                 // 64*128, d-major swizzled
    float* Ks = Qs + 64 * 128;      // 64*128, d-major swizzled
    float* Vs = Ks + 64 * 128;      // 128*64, natural
    float* Pt = Vs + 128 * 64;      // 128*128, c-major swizzled
    float4* Qs4 = (float4*)Qs;
    float4* Pt4 = (float4*)Pt;
    const ulonglong2* Ks16 = (const ulonglong2*)Ks;
    const ulonglong2* Pt16 = (const ulonglong2*)Pt;

    const int b = blockIdx.z;
    const int h = blockIdx.y;
    const int q0 = blockIdx.x * 128;
    const int tid = threadIdx.x;
    const int g = tid & 15;
    const int w = tid >> 4;          // 0..31
    const size_t base = (size_t)b * SS * EE + (size_t)h * DD;

    // Load Q tile transposed (d-major) with XOR swizzle on r-blocks.
    for (int t = tid; t < 128 * 16; t += 512) {
        const int r  = t >> 4;
        const int d4 = (t & 15) << 2;
        const float4 v = *(const float4*)(g_q + base + (size_t)(q0 + r) * EE + d4);
        const int r4 = r >> 2, rm = r & 3;
        const int sd = (d4 >> 3) & 7;
        Qs[((d4 + 0) << 7) + ((r4 ^ sd) << 2) + rm] = v.x;
        Qs[((d4 + 1) << 7) + ((r4 ^ sd) << 2) + rm] = v.y;
        Qs[((d4 + 2) << 7) + ((r4 ^ sd) << 2) + rm] = v.z;
        Qs[((d4 + 3) << 7) + ((r4 ^ sd) << 2) + rm] = v.w;
    }

    float mrow[4], lrs[4];
    u64 o2[2][4];                    // q-row pairs (4w+2j2,+1) x d g*4+dd
#pragma unroll
    for (int j = 0; j < 4; j++) { mrow[j] = -1e30f; lrs[j] = 0.0f; }
#pragma unroll
    for (int j2 = 0; j2 < 2; j2++)
#pragma unroll
        for (int dd = 0; dd < 4; dd++) o2[j2][dd] = 0ULL;

    for (int kt = 0; kt < SS; kt += 128) {
        __syncthreads();

        // Load K (transposed+swizzled) and V (natural) tiles
        for (int t = tid; t < 128 * 16; t += 512) {
            const int r  = t >> 4;
            const int d4 = (t & 15) << 2;
            const size_t goff = base + (size_t)(kt + r) * EE + d4;
            const float4 kv = *(const float4*)(g_k + goff);
            const int r4 = r >> 2, rm = r & 3;
            const int sd = (d4 >> 3) & 7;
            Ks[((d4 + 0) << 7) + ((r4 ^ sd) << 2) + rm] = kv.x;
            Ks[((d4 + 1) << 7) + ((r4 ^ sd) << 2) + rm] = kv.y;
            Ks[((d4 + 2) << 7) + ((r4 ^ sd) << 2) + rm] = kv.z;
            Ks[((d4 + 3) << 7) + ((r4 ^ sd) << 2) + rm] = kv.w;
            const float4 vv = *(const float4*)(g_v + goff);
            *(float4*)&Vs[(r << 6) + d4] = vv;
        }
        __syncthreads();

        // ---- S^T tile: pairs along k; acc2[i2][j] ----
        u64 acc2[4][4];
#pragma unroll
        for (int i2 = 0; i2 < 4; i2++)
#pragma unroll
            for (int j = 0; j < 4; j++) acc2[i2][j] = 0ULL;

#pragma unroll 8
        for (int d = 0; d < 64; d++) {
            const int sd = (d >> 3) & 7;
            const ulonglong2 ka = Ks16[(d << 5) + ((g * 2) ^ sd)];
            const ulonglong2 kb = Ks16[(d << 5) + ((g * 2 + 1) ^ sd)];
            const float4 qa = Qs4[(d << 5) + (w ^ sd)];
            const u64 kp[4] = {ka.x, ka.y, kb.x, kb.y};
            const u64 qd[4] = {dup2(qa.x), dup2(qa.y), dup2(qa.z), dup2(qa.w)};
#pragma unroll
            for (int i2 = 0; i2 < 4; i2++)
#pragma unroll
                for (int j = 0; j < 4; j++)
                    fma2(acc2[i2][j], kp[i2], qd[j]);
        }

        float Sf[8][4];
#pragma unroll
        for (int i2 = 0; i2 < 4; i2++)
#pragma unroll
            for (int j = 0; j < 4; j++)
                unpack2(Sf[2 * i2][j], Sf[2 * i2 + 1][j], acc2[i2][j]);

#pragma unroll
        for (int i = 0; i < 8; i++)
#pragma unroll
            for (int j = 0; j < 4; j++)
                Sf[i][j] = floorf(Sf[i][j] * 0.125f);

        float mt[4];
#pragma unroll
        for (int j = 0; j < 4; j++) {
            float m = Sf[0][j];
#pragma unroll
            for (int i = 1; i < 8; i++) m = fmaxf(m, Sf[i][j]);
            mt[j] = m;
        }
#pragma unroll
        for (int off = 8; off >= 1; off >>= 1)
#pragma unroll
            for (int j = 0; j < 4; j++)
                mt[j] = fmaxf(mt[j], __shfl_xor_sync(0xffffffffu, mt[j], off));

        float scj[4], rs[4];
#pragma unroll
        for (int j = 0; j < 4; j++) {
            const float mn = fmaxf(mrow[j], mt[j]);
            scj[j] = __expf(mrow[j] - mn);
            mrow[j] = mn;
            float s = 0.0f;
#pragma unroll
            for (int i = 0; i < 8; i++) {
                Sf[i][j] = __expf(Sf[i][j] - mn);
                s += Sf[i][j];
            }
            rs[j] = s;
        }
#pragma unroll
        for (int off = 8; off >= 1; off >>= 1)
#pragma unroll
            for (int j = 0; j < 4; j++)
                rs[j] += __shfl_xor_sync(0xffffffffu, rs[j], off);
#pragma unroll
        for (int j = 0; j < 4; j++)
            lrs[j] = lrs[j] * scj[j] + rs[j];
#pragma unroll
        for (int j2 = 0; j2 < 2; j2++) {
            const u64 sc2 = pack2(scj[2 * j2], scj[2 * j2 + 1]);
#pragma unroll
            for (int dd = 0; dd < 4; dd++)
                o2[j2][dd] = mul2(o2[j2][dd], sc2);
        }

        // Store P^T (c-major, q float4-contiguous, swizzled)
#pragma unroll
        for (int i = 0; i < 8; i++) {
            const int c = g * 8 + i;
            const int sw = g & 7;   // (c>>3)&7
            Pt4[(c << 5) + (w ^ sw)] =
                make_float4(Sf[i][0], Sf[i][1], Sf[i][2], Sf[i][3]);
        }
        __syncthreads();

        // O += P V; pairs along q
#pragma unroll 8
        for (int k = 0; k < 128; k++) {
            const int sw = (k >> 3) & 7;
            const ulonglong2 pA = Pt16[(k << 5) + (w ^ sw)];
            const float4 vv = *(const float4*)&Vs[(k << 6) + (g << 2)];
            const u64 pp[2] = {pA.x, pA.y};
            const u64 vd[4] = {dup2(vv.x), dup2(vv.y), dup2(vv.z), dup2(vv.w)};
#pragma unroll
            for (int j2 = 0; j2 < 2; j2++)
#pragma unroll
                for (int dd = 0; dd < 4; dd++)
                    fma2(o2[j2][dd], pp[j2], vd[dd]);
        }
    }

    // Epilogue: normalize and store. Out col = h*64 + g*4 + dd
#pragma unroll
    for (int j = 0; j < 4; j++) {
        const int j2 = j >> 1;
        const float inv = 1.0f / lrs[j];
        float o[4];
#pragma unroll
        for (int dd = 0; dd < 4; dd++) {
            float lo, hi;
            unpack2(lo, hi, o2[j2][dd]);
            o[dd] = (j & 1) ? hi : lo;
        }
        const int r = q0 + w * 4 + j;
        *(float4*)(Out + base + (size_t)r * EE + (g << 2)) =
            make_float4(o[0] * inv, o[1] * inv, o[2] * inv, o[3] * inv);
    }
}

// ---------------------------------------------------------------------------
extern "C" void kernel_launch(void* const* d_in, const int* in_sizes, int n_in,
                              void* d_out, int out_size)
{
    const float* key   = (const float*)d_in[0];
    const float* query = (const float*)d_in[1];
    const float* value = (const float*)d_in[2];
    const float* Wq    = (const float*)d_in[3];
    const float* bq    = (const float*)d_in[4];
    const float* Wk    = (const float*)d_in[5];
    const float* bk    = (const float*)d_in[6];
    const float* Wv    = (const float*)d_in[7];
    const float* bv    = (const float*)d_in[8];
    float* out = (float*)d_out;

    void *pq = 0, *pk = 0, *pv = 0;
    cudaGetSymbolAddress(&pq, g_q);
    cudaGetSymbolAddress(&pk, g_k);
    cudaGetSymbolAddress(&pv, g_v);

    cudaFuncSetAttribute(proj_mma, cudaFuncAttributeMaxDynamicSharedMemorySize,
                         PROJ_SMEM);
    const int ATTN_SMEM = (64 * 128 + 64 * 128 + 128 * 64 + 128 * 128) * 4; // 160 KB
    cudaFuncSetAttribute(attn2, cudaFuncAttributeMaxDynamicSharedMemorySize,
                         ATTN_SMEM);

    dim3 sgrid(MM * EE / 1024, 3);
    split_act<<<sgrid, 256>>>(query, key, value);
    dim3 wgrid(EE * EE / 1024, 3);
    split_w<<<wgrid, 256>>>(Wq, Wk, Wv);

    dim3 pgrid(EE / 128, MM / 128, 3);
    proj_mma<<<pgrid, 256, PROJ_SMEM>>>(bq, bk, bv,
                                        (float*)pq, (float*)pk, (float*)pv);

    dim3 agrid(SS / 128, HH, BB);
    attn2<<<agrid, 512, ATTN_SMEM>>>(out);
}

// round 12
// speedup vs baseline: 1.4824x; 1.2393x over previous
#include <cuda_runtime.h>
#include <cuda_bf16.h>
#include <math.h>
#include <stdint.h>

#define BB 4
#define SS 2048
#define EE 1024
#define HH 16
#define DD 64
#define MM (BB*SS)

typedef unsigned long long u64;

// Projected q, k, v fp32: [B*S, E] row-major (col = h*64 + d)
__device__ float g_q[MM * EE];
__device__ float g_k[MM * EE];
__device__ float g_v[MM * EE];

// bf16 split planes of inputs (for proj GEMMs)
__device__ uint16_t g_sa[3][3][MM * EE];
__device__ uint16_t g_sw[3][3][EE * EE];

// ===========================================================================
// helpers
// ===========================================================================
__device__ __forceinline__ uint32_t smem_u32(const void* p) {
    uint32_t a;
    asm("{ .reg .u64 t; cvta.to.shared.u64 t, %1; cvt.u32.u64 %0, t; }"
        : "=r"(a) : "l"(p));
    return a;
}
__device__ __forceinline__ uint32_t sw128(uint32_t off) {
    return off ^ ((off >> 3) & 0x70);
}
__device__ __forceinline__ void split3(float x, uint16_t& b0, uint16_t& b1, uint16_t& b2) {
    __nv_bfloat16 h0 = __float2bfloat16_rn(x);
    float r = x - __bfloat162float(h0);
    __nv_bfloat16 h1 = __float2bfloat16_rn(r);
    r -= __bfloat162float(h1);
    __nv_bfloat16 h2 = __float2bfloat16_rn(r);
    b0 = __bfloat16_as_ushort(h0);
    b1 = __bfloat16_as_ushort(h1);
    b2 = __bfloat16_as_ushort(h2);
}
__device__ __forceinline__ void ldsm4(uint32_t* r, uint32_t addr) {
    asm volatile("ldmatrix.sync.aligned.m8n8.x4.shared.b16 {%0,%1,%2,%3}, [%4];"
        : "=r"(r[0]), "=r"(r[1]), "=r"(r[2]), "=r"(r[3]) : "r"(addr));
}
// chained accumulate (correction chains only — small magnitude)
__device__ __forceinline__ void mma16816(float* c, const uint32_t* a,
                                         uint32_t b0, uint32_t b1) {
    asm volatile("mma.sync.aligned.m16n8k16.row.col.f32.bf16.bf16.f32 "
        "{%0,%1,%2,%3}, {%4,%5,%6,%7}, {%8,%9}, {%0,%1,%2,%3};"
        : "+f"(c[0]), "+f"(c[1]), "+f"(c[2]), "+f"(c[3])
        : "r"(a[0]), "r"(a[1]), "r"(a[2]), "r"(a[3]), "r"(b0), "r"(b1));
}
// Zero-C variant: d = A*B (k16 partial only) — main chain uses this + FADD drain
__device__ __forceinline__ void mma16816_z(float* d, const uint32_t* a,
                                           uint32_t b0, uint32_t b1) {
    asm volatile("mma.sync.aligned.m16n8k16.row.col.f32.bf16.bf16.f32 "
        "{%0,%1,%2,%3}, {%4,%5,%6,%7}, {%8,%9}, {%10,%11,%12,%13};"
        : "=f"(d[0]), "=f"(d[1]), "=f"(d[2]), "=f"(d[3])
        : "r"(a[0]), "r"(a[1]), "r"(a[2]), "r"(a[3]), "r"(b0), "r"(b1),
          "f"(0.0f), "f"(0.0f), "f"(0.0f), "f"(0.0f));
}
// packed f32x2
__device__ __forceinline__ void fma2(u64& c, u64 a, u64 b) {
    asm("fma.rn.f32x2 %0, %1, %2, %0;" : "+l"(c) : "l"(a), "l"(b));
}
__device__ __forceinline__ u64 mul2(u64 a, u64 b) {
    u64 c;
    asm("mul.rn.f32x2 %0, %1, %2;" : "=l"(c) : "l"(a), "l"(b));
    return c;
}
__device__ __forceinline__ u64 pack2(float l, float h) {
    u64 o;
    asm("mov.b64 %0, {%1, %2};" : "=l"(o) : "f"(l), "f"(h));
    return o;
}
__device__ __forceinline__ u64 dup2(float x) {
    u64 o;
    asm("mov.b64 %0, {%1, %1};" : "=l"(o) : "f"(x));
    return o;
}
__device__ __forceinline__ void unpack2(float& l, float& h, u64 u) {
    asm("mov.b64 {%0, %1}, %2;" : "=f"(l), "=f"(h) : "l"(u));
}
#define CPASYNC16(s, g) \
    asm volatile("cp.async.cg.shared.global [%0], [%1], 16;" :: "r"(s), "l"(g))
#define CP_COMMIT() asm volatile("cp.async.commit_group;" ::: "memory")
#define CP_WAIT1()  asm volatile("cp.async.wait_group 1;" ::: "memory")
#define CP_WAIT0()  asm volatile("cp.async.wait_group 0;" ::: "memory")

// ===========================================================================
// Split conversion kernels (inputs only)
// ===========================================================================
__global__ __launch_bounds__(256)
void split_act(const float* __restrict__ q, const float* __restrict__ k,
               const float* __restrict__ v)
{
    const int z = blockIdx.y;
    const float* src = (z == 0) ? q : (z == 1) ? k : v;
    const size_t i = ((size_t)blockIdx.x * 256 + threadIdx.x) * 4;
    const float4 x = *(const float4*)(src + i);
    uint16_t b0[4], b1[4], b2[4];
    split3(x.x, b0[0], b1[0], b2[0]);
    split3(x.y, b0[1], b1[1], b2[1]);
    split3(x.z, b0[2], b1[2], b2[2]);
    split3(x.w, b0[3], b1[3], b2[3]);
    *(ushort4*)&g_sa[z][0][i] = make_ushort4(b0[0], b0[1], b0[2], b0[3]);
    *(ushort4*)&g_sa[z][1][i] = make_ushort4(b1[0], b1[1], b1[2], b1[3]);
    *(ushort4*)&g_sa[z][2][i] = make_ushort4(b2[0], b2[1], b2[2], b2[3]);
}

__global__ __launch_bounds__(256)
void split_w(const float* __restrict__ wq, const float* __restrict__ wk,
             const float* __restrict__ wv)
{
    const int z = blockIdx.y;
    const float* src = (z == 0) ? wq : (z == 1) ? wk : wv;
    const size_t i = ((size_t)blockIdx.x * 256 + threadIdx.x) * 4;
    const float4 x = *(const float4*)(src + i);
    uint16_t b0[4], b1[4], b2[4];
    split3(x.x, b0[0], b1[0], b2[0]);
    split3(x.y, b0[1], b1[1], b2[1]);
    split3(x.z, b0[2], b1[2], b2[2]);
    split3(x.w, b0[3], b1[3], b2[3]);
    *(ushort4*)&g_sw[z][0][i] = make_ushort4(b0[0], b0[1], b0[2], b0[3]);
    *(ushort4*)&g_sw[z][1][i] = make_ushort4(b1[0], b1[1], b1[2], b1[3]);
    *(ushort4*)&g_sw[z][2][i] = make_ushort4(b2[0], b2[1], b2[2], b2[3]);
}

// ===========================================================================
// Projection GEMM via mma.sync, bf16-split (R11 — VALIDATED):
// main chain (0,0) issued with C=0 and drained into accH via fp32 RN FADD;
// correction chains -> accL (chained). Q/K: 5 corrections. V: 2.
// ===========================================================================
#define TILE_B   16384
#define STAGE_B  (6 * TILE_B)
#define PROJ_SMEM (2 * STAGE_B)
#define KT_STEPS 16

__global__ __launch_bounds__(256, 1)
void proj_mma(const float* __restrict__ bq, const float* __restrict__ bk,
              const float* __restrict__ bv,
              float* __restrict__ Cq, float* __restrict__ Ck,
              float* __restrict__ Cv)
{
    extern __shared__ char smem[];
    const uint32_t sb = smem_u32(smem);
    const int tid = threadIdx.x;
    const int wid = tid >> 5;
    const int l   = tid & 31;
    const int wm = wid >> 2;
    const int wn = wid & 3;

    const int z  = blockIdx.z;
    const int bn = blockIdx.x * 128;
    const int bm = blockIdx.y * 128;
    const float* bias = (z == 0) ? bq : (z == 1) ? bk : bv;
    float*       C    = (z == 0) ? Cq : (z == 1) ? Ck : Cv;
    const int ncorr = (z == 2) ? 2 : 5;

    uint32_t swA[4], swB[2];
#pragma unroll
    for (int mi = 0; mi < 4; mi++)
        swA[mi] = sw128((uint32_t)((wm * 64 + mi * 16 + (l & 15)) * 128
                                   + ((l >> 4) << 4)));
#pragma unroll
    for (int nh = 0; nh < 2; nh++)
        swB[nh] = sw128((uint32_t)((wn * 32 + nh * 16 + ((l >> 4) & 1) * 8
                                    + (l & 7)) * 128 + (((l >> 3) & 1) << 4)));

    float accH[4][4][4];
    float accL[4][4][4];
#pragma unroll
    for (int mi = 0; mi < 4; mi++)
#pragma unroll
        for (int ni = 0; ni < 4; ni++)
#pragma unroll
            for (int c = 0; c < 4; c++) {
                accH[mi][ni][c] = 0.0f;
                accL[mi][ni][c] = 0.0f;
            }

    auto load_stage = [&](int kt, int st) {
        const uint32_t stage = sb + st * STAGE_B;
#pragma unroll
        for (int i = 0; i < 24; i++) {
            const int idx = tid + i * 256;
            const int plane = idx >> 10;
            const int chunk = idx & 1023;
            const int r = chunk >> 3;
            const int c = chunk & 7;
            const uint16_t* gp = (plane < 3)
                ? &g_sa[z][plane][(size_t)(bm + r) * EE + kt * 64 + c * 8]
                : &g_sw[z][plane - 3][(size_t)(bn + r) * EE + kt * 64 + c * 8];
            const uint32_t s = stage + plane * TILE_B + sw128((uint32_t)(r * 128 + c * 16));
            CPASYNC16(s, gp);
        }
        CP_COMMIT();
    };

    load_stage(0, 0);

    const int pa[5] = {1, 0, 2, 1, 0};
    const int pb[5] = {0, 1, 0, 1, 2};

    for (int kt = 0; kt < KT_STEPS; kt++) {
        if (kt + 1 < KT_STEPS) {
            load_stage(kt + 1, (kt + 1) & 1);
            CP_WAIT1();
        } else {
            CP_WAIT0();
        }
        __syncthreads();

        const uint32_t As = sb + (kt & 1) * STAGE_B;
        const uint32_t Bs = As + 3 * TILE_B;

        // ---- main chain (0,0): C=0 HMMA + fp32 RN drain ----
#pragma unroll
        for (int ks = 0; ks < 4; ks++) {
            const uint32_t kx = (uint32_t)(ks << 5);
            uint32_t a[4][4], b[2][4];
#pragma unroll
            for (int mi = 0; mi < 4; mi++)
                ldsm4(a[mi], As + (swA[mi] ^ kx));
#pragma unroll
            for (int nh = 0; nh < 2; nh++)
                ldsm4(b[nh], Bs + (swB[nh] ^ kx));
#pragma unroll
            for (int mi = 0; mi < 4; mi++) {
#pragma unroll
                for (int ni = 0; ni < 4; ni++) {
                    float t[4];
                    const uint32_t bb0 = b[ni >> 1][(ni & 1) * 2];
                    const uint32_t bb1 = b[ni >> 1][(ni & 1) * 2 + 1];
                    mma16816_z(t, a[mi], bb0, bb1);
                    accH[mi][ni][0] += t[0];
                    accH[mi][ni][1] += t[1];
                    accH[mi][ni][2] += t[2];
                    accH[mi][ni][3] += t[3];
                }
            }
        }

        // ---- correction chains -> accL (chained) ----
        for (int p = 0; p < ncorr; p++) {
            const uint32_t at = As + pa[p] * TILE_B;
            const uint32_t bt = Bs + pb[p] * TILE_B;
#pragma unroll
            for (int ks = 0; ks < 4; ks++) {
                const uint32_t kx = (uint32_t)(ks << 5);
                uint32_t a[4][4], b[2][4];
#pragma unroll
                for (int mi = 0; mi < 4; mi++)
                    ldsm4(a[mi], at + (swA[mi] ^ kx));
#pragma unroll
                for (int nh = 0; nh < 2; nh++)
                    ldsm4(b[nh], bt + (swB[nh] ^ kx));
#pragma unroll
                for (int mi = 0; mi < 4; mi++) {
                    mma16816(accL[mi][0], a[mi], b[0][0], b[0][1]);
                    mma16816(accL[mi][1], a[mi], b[0][2], b[0][3]);
                    mma16816(accL[mi][2], a[mi], b[1][0], b[1][1]);
                    mma16816(accL[mi][3], a[mi], b[1][2], b[1][3]);
                }
            }
        }
        __syncthreads();
    }

#pragma unroll
    for (int mi = 0; mi < 4; mi++) {
        const int r0 = bm + wm * 64 + mi * 16 + (l >> 2);
#pragma unroll
        for (int ni = 0; ni < 4; ni++) {
            const int cb = bn + wn * 32 + ni * 8 + 2 * (l & 3);
            const float bx = bias[cb], by = bias[cb + 1];
            float2 v0 = make_float2(accH[mi][ni][0] + accL[mi][ni][0] + bx,
                                    accH[mi][ni][1] + accL[mi][ni][1] + by);
            float2 v1 = make_float2(accH[mi][ni][2] + accL[mi][ni][2] + bx,
                                    accH[mi][ni][3] + accL[mi][ni][3] + by);
            *(float2*)(C + (size_t)r0 * EE + cb) = v0;
            *(float2*)(C + (size_t)(r0 + 8) * EE + cb) = v1;
        }
    }
}

// ===========================================================================
// Flash attention, f32x2, 256 threads (R8 — measured 1585us, bitwise R1).
// S phase: thread (g=tid&15, w=tid>>4) owns k-cols g*8..+7, q-rows w*8..+7.
// PV phase: rows w*8..+7, d-cols g*4..+3.
// ===========================================================================
__global__ __launch_bounds__(256, 1)
void attn2(float* __restrict__ Out)
{
    extern __shared__ float sm[];
    float* Qs = sm;                 // 64*128, d-major swizzled
    float* Ks = Qs + 64 * 128;      // 64*128, d-major swizzled
    float* Vs = Ks + 64 * 128;      // 128*64, natural
    float* Pt = Vs + 128 * 64;      // 128*128, c-major swizzled
    float4* Qs4 = (float4*)Qs;
    float4* Pt4 = (float4*)Pt;
    const ulonglong2* Ks16 = (const ulonglong2*)Ks;
    const ulonglong2* Pt16 = (const ulonglong2*)Pt;

    const int b = blockIdx.z;
    const int h = blockIdx.y;
    const int q0 = blockIdx.x * 128;
    const int tid = threadIdx.x;
    const int g = tid & 15;
    const int w = tid >> 4;
    const size_t base = (size_t)b * SS * EE + (size_t)h * DD;

    // Load Q tile transposed (d-major) with XOR swizzle on r-blocks.
    for (int t = tid; t < 128 * 16; t += 256) {
        const int r  = t >> 4;
        const int d4 = (t & 15) << 2;
        const float4 v = *(const float4*)(g_q + base + (size_t)(q0 + r) * EE + d4);
        const int r4 = r >> 2, rm = r & 3;
        const int sd = (d4 >> 3) & 7;
        Qs[((d4 + 0) << 7) + ((r4 ^ sd) << 2) + rm] = v.x;
        Qs[((d4 + 1) << 7) + ((r4 ^ sd) << 2) + rm] = v.y;
        Qs[((d4 + 2) << 7) + ((r4 ^ sd) << 2) + rm] = v.z;
        Qs[((d4 + 3) << 7) + ((r4 ^ sd) << 2) + rm] = v.w;
    }

    float mrow[8], lrs[8];
    u64 o2[4][4];                   // q-row pairs x 4 d-cols
#pragma unroll
    for (int j = 0; j < 8; j++) { mrow[j] = -1e30f; lrs[j] = 0.0f; }
#pragma unroll
    for (int j2 = 0; j2 < 4; j2++)
#pragma unroll
        for (int dd = 0; dd < 4; dd++) o2[j2][dd] = 0ULL;

    for (int kt = 0; kt < SS; kt += 128) {
        __syncthreads();

        // Load K (transposed+swizzled) and V (natural) tiles
        for (int t = tid; t < 128 * 16; t += 256) {
            const int r  = t >> 4;
            const int d4 = (t & 15) << 2;
            const size_t goff = base + (size_t)(kt + r) * EE + d4;
            const float4 kv = *(const float4*)(g_k + goff);
            const int r4 = r >> 2, rm = r & 3;
            const int sd = (d4 >> 3) & 7;
            Ks[((d4 + 0) << 7) + ((r4 ^ sd) << 2) + rm] = kv.x;
            Ks[((d4 + 1) << 7) + ((r4 ^ sd) << 2) + rm] = kv.y;
            Ks[((d4 + 2) << 7) + ((r4 ^ sd) << 2) + rm] = kv.z;
            Ks[((d4 + 3) << 7) + ((r4 ^ sd) << 2) + rm] = kv.w;
            const float4 vv = *(const float4*)(g_v + goff);
            *(float4*)&Vs[(r << 6) + d4] = vv;
        }
        __syncthreads();

        // ---- S^T tile: pairs along k; acc2[i2][j] ----
        u64 acc2[4][8];
#pragma unroll
        for (int i2 = 0; i2 < 4; i2++)
#pragma unroll
            for (int j = 0; j < 8; j++) acc2[i2][j] = 0ULL;

#pragma unroll 8
        for (int d = 0; d < 64; d++) {
            const int sd = (d >> 3) & 7;
            const ulonglong2 ka = Ks16[(d << 5) + ((g * 2) ^ sd)];
            const ulonglong2 kb = Ks16[(d << 5) + ((g * 2 + 1) ^ sd)];
            const float4 qa = Qs4[(d << 5) + ((w * 2) ^ sd)];
            const float4 qb = Qs4[(d << 5) + ((w * 2 + 1) ^ sd)];
            const u64 kp[4] = {ka.x, ka.y, kb.x, kb.y};
            const u64 qd[8] = {dup2(qa.x), dup2(qa.y), dup2(qa.z), dup2(qa.w),
                               dup2(qb.x), dup2(qb.y), dup2(qb.z), dup2(qb.w)};
#pragma unroll
            for (int i2 = 0; i2 < 4; i2++)
#pragma unroll
                for (int j = 0; j < 8; j++)
                    fma2(acc2[i2][j], kp[i2], qd[j]);
        }

        // Unpack (register aliasing) to Sf[i][j], i = k-col offset 0..7
        float Sf[8][8];
#pragma unroll
        for (int i2 = 0; i2 < 4; i2++)
#pragma unroll
            for (int j = 0; j < 8; j++)
                unpack2(Sf[2 * i2][j], Sf[2 * i2 + 1][j], acc2[i2][j]);

        // scores = floor(dot / 8)
#pragma unroll
        for (int i = 0; i < 8; i++)
#pragma unroll
            for (int j = 0; j < 8; j++)
                Sf[i][j] = floorf(Sf[i][j] * 0.125f);

        // Row max over the 128 k-cols of each q-row
        float mt[8];
#pragma unroll
        for (int j = 0; j < 8; j++) {
            float m = Sf[0][j];
#pragma unroll
            for (int i = 1; i < 8; i++) m = fmaxf(m, Sf[i][j]);
            mt[j] = m;
        }
#pragma unroll
        for (int off = 8; off >= 1; off >>= 1)
#pragma unroll
            for (int j = 0; j < 8; j++)
                mt[j] = fmaxf(mt[j], __shfl_xor_sync(0xffffffffu, mt[j], off));

        float scj[8], rs[8];
#pragma unroll
        for (int j = 0; j < 8; j++) {
            const float mn = fmaxf(mrow[j], mt[j]);
            scj[j] = __expf(mrow[j] - mn);   // 0 on first tile
            mrow[j] = mn;
            float s = 0.0f;
#pragma unroll
            for (int i = 0; i < 8; i++) {
                Sf[i][j] = __expf(Sf[i][j] - mn);
                s += Sf[i][j];
            }
            rs[j] = s;
        }
#pragma unroll
        for (int off = 8; off >= 1; off >>= 1)
#pragma unroll
            for (int j = 0; j < 8; j++)
                rs[j] += __shfl_xor_sync(0xffffffffu, rs[j], off);
#pragma unroll
        for (int j = 0; j < 8; j++)
            lrs[j] = lrs[j] * scj[j] + rs[j];
#pragma unroll
        for (int j2 = 0; j2 < 4; j2++) {
            const u64 sc2 = pack2(scj[2 * j2], scj[2 * j2 + 1]);
#pragma unroll
            for (int dd = 0; dd < 4; dd++)
                o2[j2][dd] = mul2(o2[j2][dd], sc2);
        }

        // Store P^T (c-major, q float4-contiguous, swizzled)
#pragma unroll
        for (int i = 0; i < 8; i++) {
            const int c = g * 8 + i;
            const int sw = g & 7;   // (c>>3)&7
            Pt4[(c << 5) + ((w * 2) ^ sw)] =
                make_float4(Sf[i][0], Sf[i][1], Sf[i][2], Sf[i][3]);
            Pt4[(c << 5) + ((w * 2 + 1) ^ sw)] =
                make_float4(Sf[i][4], Sf[i][5], Sf[i][6], Sf[i][7]);
        }
        __syncthreads();

        // O += P V; pairs along q: o2[j2][dd], rows (8w+2j2, +1), d = 4g+dd
#pragma unroll 8
        for (int k = 0; k < 128; k++) {
            const int sw = (k >> 3) & 7;
            const ulonglong2 pA = Pt16[(k << 5) + ((w * 2) ^ sw)];
            const ulonglong2 pB = Pt16[(k << 5) + ((w * 2 + 1) ^ sw)];
            const float4 vv = *(const float4*)&Vs[(k << 6) + (g << 2)];
            const u64 pp[4] = {pA.x, pA.y, pB.x, pB.y};
            const u64 vd[4] = {dup2(vv.x), dup2(vv.y), dup2(vv.z), dup2(vv.w)};
#pragma unroll
            for (int j2 = 0; j2 < 4; j2++)
#pragma unroll
                for (int dd = 0; dd < 4; dd++)
                    fma2(o2[j2][dd], pp[j2], vd[dd]);
        }
    }

    // Epilogue: normalize and store. Out col = h*64 + g*4 + dd
#pragma unroll
    for (int j = 0; j < 8; j++) {
        const int j2 = j >> 1;
        const float inv = 1.0f / lrs[j];
        float o[4];
#pragma unroll
        for (int dd = 0; dd < 4; dd++) {
            float lo, hi;
            unpack2(lo, hi, o2[j2][dd]);
            o[dd] = (j & 1) ? hi : lo;
        }
        const int r = q0 + w * 8 + j;
        *(float4*)(Out + base + (size_t)r * EE + (g << 2)) =
            make_float4(o[0] * inv, o[1] * inv, o[2] * inv, o[3] * inv);
    }
}

// ---------------------------------------------------------------------------
extern "C" void kernel_launch(void* const* d_in, const int* in_sizes, int n_in,
                              void* d_out, int out_size)
{
    const float* key   = (const float*)d_in[0];
    const float* query = (const float*)d_in[1];
    const float* value = (const float*)d_in[2];
    const float* Wq    = (const float*)d_in[3];
    const float* bq    = (const float*)d_in[4];
    const float* Wk    = (const float*)d_in[5];
    const float* bk    = (const float*)d_in[6];
    const float* Wv    = (const float*)d_in[7];
    const float* bv    = (const float*)d_in[8];
    float* out = (float*)d_out;

    void *pq = 0, *pk = 0, *pv = 0;
    cudaGetSymbolAddress(&pq, g_q);
    cudaGetSymbolAddress(&pk, g_k);
    cudaGetSymbolAddress(&pv, g_v);

    cudaFuncSetAttribute(proj_mma, cudaFuncAttributeMaxDynamicSharedMemorySize,
                         PROJ_SMEM);
    const int ATTN_SMEM = (64 * 128 + 64 * 128 + 128 * 64 + 128 * 128) * 4; // 160 KB
    cudaFuncSetAttribute(attn2, cudaFuncAttributeMaxDynamicSharedMemorySize,
                         ATTN_SMEM);

    dim3 sgrid(MM * EE / 1024, 3);
    split_act<<<sgrid, 256>>>(query, key, value);
    dim3 wgrid(EE * EE / 1024, 3);
    split_w<<<wgrid, 256>>>(Wq, Wk, Wv);

    dim3 pgrid(EE / 128, MM / 128, 3);
    proj_mma<<<pgrid, 256, PROJ_SMEM>>>(bq, bk, bv,
                                        (float*)pq, (float*)pk, (float*)pv);

    dim3 agrid(SS / 128, HH, BB);
    attn2<<<agrid, 256, ATTN_SMEM>>>(out);
}

// round 13
// speedup vs baseline: 1.6607x; 1.1202x over previous
#include <cuda_runtime.h>
#include <cuda_bf16.h>
#include <math.h>
#include <stdint.h>

#define BB 4
#define SS 2048
#define EE 1024
#define HH 16
#define DD 64
#define MM (BB*SS)

typedef unsigned long long u64;

// Projected q, k, v fp32: [B*S, E] row-major (col = h*64 + d)
__device__ float g_q[MM * EE];
__device__ float g_k[MM * EE];
__device__ float g_v[MM * EE];
// K transposed per (b,h): [b*HH+h][d][s]  (for cp.async-friendly attn loads)
__device__ float g_kT[(size_t)BB * HH * DD * SS];

// bf16 split planes of inputs (for proj GEMMs)
__device__ uint16_t g_sa[3][3][MM * EE];
__device__ uint16_t g_sw[3][3][EE * EE];

// ===========================================================================
// helpers
// ===========================================================================
__device__ __forceinline__ uint32_t smem_u32(const void* p) {
    uint32_t a;
    asm("{ .reg .u64 t; cvta.to.shared.u64 t, %1; cvt.u32.u64 %0, t; }"
        : "=r"(a) : "l"(p));
    return a;
}
__device__ __forceinline__ uint32_t sw128(uint32_t off) {
    return off ^ ((off >> 3) & 0x70);
}
__device__ __forceinline__ void split3(float x, uint16_t& b0, uint16_t& b1, uint16_t& b2) {
    __nv_bfloat16 h0 = __float2bfloat16_rn(x);
    float r = x - __bfloat162float(h0);
    __nv_bfloat16 h1 = __float2bfloat16_rn(r);
    r -= __bfloat162float(h1);
    __nv_bfloat16 h2 = __float2bfloat16_rn(r);
    b0 = __bfloat16_as_ushort(h0);
    b1 = __bfloat16_as_ushort(h1);
    b2 = __bfloat16_as_ushort(h2);
}
__device__ __forceinline__ void ldsm4(uint32_t* r, uint32_t addr) {
    asm volatile("ldmatrix.sync.aligned.m8n8.x4.shared.b16 {%0,%1,%2,%3}, [%4];"
        : "=r"(r[0]), "=r"(r[1]), "=r"(r[2]), "=r"(r[3]) : "r"(addr));
}
// chained accumulate (correction chains only — small magnitude)
__device__ __forceinline__ void mma16816(float* c, const uint32_t* a,
                                         uint32_t b0, uint32_t b1) {
    asm volatile("mma.sync.aligned.m16n8k16.row.col.f32.bf16.bf16.f32 "
        "{%0,%1,%2,%3}, {%4,%5,%6,%7}, {%8,%9}, {%0,%1,%2,%3};"
        : "+f"(c[0]), "+f"(c[1]), "+f"(c[2]), "+f"(c[3])
        : "r"(a[0]), "r"(a[1]), "r"(a[2]), "r"(a[3]), "r"(b0), "r"(b1));
}
// Zero-C variant: d = A*B (k16 partial only) — main chain uses this + FADD drain
__device__ __forceinline__ void mma16816_z(float* d, const uint32_t* a,
                                           uint32_t b0, uint32_t b1) {
    asm volatile("mma.sync.aligned.m16n8k16.row.col.f32.bf16.bf16.f32 "
        "{%0,%1,%2,%3}, {%4,%5,%6,%7}, {%8,%9}, {%10,%11,%12,%13};"
        : "=f"(d[0]), "=f"(d[1]), "=f"(d[2]), "=f"(d[3])
        : "r"(a[0]), "r"(a[1]), "r"(a[2]), "r"(a[3]), "r"(b0), "r"(b1),
          "f"(0.0f), "f"(0.0f), "f"(0.0f), "f"(0.0f));
}
// packed f32x2
__device__ __forceinline__ void fma2(u64& c, u64 a, u64 b) {
    asm("fma.rn.f32x2 %0, %1, %2, %0;" : "+l"(c) : "l"(a), "l"(b));
}
__device__ __forceinline__ u64 mul2(u64 a, u64 b) {
    u64 c;
    asm("mul.rn.f32x2 %0, %1, %2;" : "=l"(c) : "l"(a), "l"(b));
    return c;
}
__device__ __forceinline__ u64 pack2(float l, float h) {
    u64 o;
    asm("mov.b64 %0, {%1, %2};" : "=l"(o) : "f"(l), "f"(h));
    return o;
}
__device__ __forceinline__ u64 dup2(float x) {
    u64 o;
    asm("mov.b64 %0, {%1, %1};" : "=l"(o) : "f"(x));
    return o;
}
__device__ __forceinline__ void unpack2(float& l, float& h, u64 u) {
    asm("mov.b64 {%0, %1}, %2;" : "=f"(l), "=f"(h) : "l"(u));
}
#define CPASYNC16(s, g) \
    asm volatile("cp.async.cg.shared.global [%0], [%1], 16;" :: "r"(s), "l"(g))
#define CP_COMMIT() asm volatile("cp.async.commit_group;" ::: "memory")
#define CP_WAIT1()  asm volatile("cp.async.wait_group 1;" ::: "memory")
#define CP_WAIT0()  asm volatile("cp.async.wait_group 0;" ::: "memory")

// ===========================================================================
// Split conversion kernels (inputs only)
// ===========================================================================
__global__ __launch_bounds__(256)
void split_act(const float* __restrict__ q, const float* __restrict__ k,
               const float* __restrict__ v)
{
    const int z = blockIdx.y;
    const float* src = (z == 0) ? q : (z == 1) ? k : v;
    const size_t i = ((size_t)blockIdx.x * 256 + threadIdx.x) * 4;
    const float4 x = *(const float4*)(src + i);
    uint16_t b0[4], b1[4], b2[4];
    split3(x.x, b0[0], b1[0], b2[0]);
    split3(x.y, b0[1], b1[1], b2[1]);
    split3(x.z, b0[2], b1[2], b2[2]);
    split3(x.w, b0[3], b1[3], b2[3]);
    *(ushort4*)&g_sa[z][0][i] = make_ushort4(b0[0], b0[1], b0[2], b0[3]);
    *(ushort4*)&g_sa[z][1][i] = make_ushort4(b1[0], b1[1], b1[2], b1[3]);
    *(ushort4*)&g_sa[z][2][i] = make_ushort4(b2[0], b2[1], b2[2], b2[3]);
}

__global__ __launch_bounds__(256)
void split_w(const float* __restrict__ wq, const float* __restrict__ wk,
             const float* __restrict__ wv)
{
    const int z = blockIdx.y;
    const float* src = (z == 0) ? wq : (z == 1) ? wk : wv;
    const size_t i = ((size_t)blockIdx.x * 256 + threadIdx.x) * 4;
    const float4 x = *(const float4*)(src + i);
    uint16_t b0[4], b1[4], b2[4];
    split3(x.x, b0[0], b1[0], b2[0]);
    split3(x.y, b0[1], b1[1], b2[1]);
    split3(x.z, b0[2], b1[2], b2[2]);
    split3(x.w, b0[3], b1[3], b2[3]);
    *(ushort4*)&g_sw[z][0][i] = make_ushort4(b0[0], b0[1], b0[2], b0[3]);
    *(ushort4*)&g_sw[z][1][i] = make_ushort4(b1[0], b1[1], b1[2], b1[3]);
    *(ushort4*)&g_sw[z][2][i] = make_ushort4(b2[0], b2[1], b2[2], b2[3]);
}

// Transpose projected k per (b,h): g_kT[bh][d][s] = g_k[b*SS+s][h*64+d]
__global__ __launch_bounds__(256)
void transpose_k()
{
    __shared__ float ts[64][65];
    const int s0 = blockIdx.x * 64;
    const int bh = blockIdx.y;
    const int b = bh >> 4, h = bh & 15;
    const int t = threadIdx.x;

#pragma unroll
    for (int i = 0; i < 4; i++) {
        const int e = t + i * 256;      // 0..1023 float4s
        const int sl = e >> 4;
        const int d4 = (e & 15) * 4;
        const float4 x = *(const float4*)(g_k
            + (size_t)(b * SS + s0 + sl) * EE + h * 64 + d4);
        ts[sl][d4 + 0] = x.x; ts[sl][d4 + 1] = x.y;
        ts[sl][d4 + 2] = x.z; ts[sl][d4 + 3] = x.w;
    }
    __syncthreads();

#pragma unroll
    for (int i = 0; i < 4; i++) {
        const int e = t + i * 256;
        const int d  = e >> 4;
        const int s4 = (e & 15) * 4;
        float4 o;
        o.x = ts[s4 + 0][d]; o.y = ts[s4 + 1][d];
        o.z = ts[s4 + 2][d]; o.w = ts[s4 + 3][d];
        *(float4*)&g_kT[((size_t)bh * DD + d) * SS + s0 + s4] = o;
    }
}

// ===========================================================================
// Projection GEMM via mma.sync, bf16-split (R11 — VALIDATED):
// main chain (0,0) issued with C=0 and drained into accH via fp32 RN FADD;
// correction chains -> accL (chained). Q/K: 5 corrections. V: 2.
// ===========================================================================
#define TILE_B   16384
#define STAGE_B  (6 * TILE_B)
#define PROJ_SMEM (2 * STAGE_B)
#define KT_STEPS 16

__global__ __launch_bounds__(256, 1)
void proj_mma(const float* __restrict__ bq, const float* __restrict__ bk,
              const float* __restrict__ bv,
              float* __restrict__ Cq, float* __restrict__ Ck,
              float* __restrict__ Cv)
{
    extern __shared__ char smem[];
    const uint32_t sb = smem_u32(smem);
    const int tid = threadIdx.x;
    const int wid = tid >> 5;
    const int l   = tid & 31;
    const int wm = wid >> 2;
    const int wn = wid & 3;

    const int z  = blockIdx.z;
    const int bn = blockIdx.x * 128;
    const int bm = blockIdx.y * 128;
    const float* bias = (z == 0) ? bq : (z == 1) ? bk : bv;
    float*       C    = (z == 0) ? Cq : (z == 1) ? Ck : Cv;
    const int ncorr = (z == 2) ? 2 : 5;

    uint32_t swA[4], swB[2];
#pragma unroll
    for (int mi = 0; mi < 4; mi++)
        swA[mi] = sw128((uint32_t)((wm * 64 + mi * 16 + (l & 15)) * 128
                                   + ((l >> 4) << 4)));
#pragma unroll
    for (int nh = 0; nh < 2; nh++)
        swB[nh] = sw128((uint32_t)((wn * 32 + nh * 16 + ((l >> 4) & 1) * 8
                                    + (l & 7)) * 128 + (((l >> 3) & 1) << 4)));

    float accH[4][4][4];
    float accL[4][4][4];
#pragma unroll
    for (int mi = 0; mi < 4; mi++)
#pragma unroll
        for (int ni = 0; ni < 4; ni++)
#pragma unroll
            for (int c = 0; c < 4; c++) {
                accH[mi][ni][c] = 0.0f;
                accL[mi][ni][c] = 0.0f;
            }

    auto load_stage = [&](int kt, int st) {
        const uint32_t stage = sb + st * STAGE_B;
#pragma unroll
        for (int i = 0; i < 24; i++) {
            const int idx = tid + i * 256;
            const int plane = idx >> 10;
            const int chunk = idx & 1023;
            const int r = chunk >> 3;
            const int c = chunk & 7;
            const uint16_t* gp = (plane < 3)
                ? &g_sa[z][plane][(size_t)(bm + r) * EE + kt * 64 + c * 8]
                : &g_sw[z][plane - 3][(size_t)(bn + r) * EE + kt * 64 + c * 8];
            const uint32_t s = stage + plane * TILE_B + sw128((uint32_t)(r * 128 + c * 16));
            CPASYNC16(s, gp);
        }
        CP_COMMIT();
    };

    load_stage(0, 0);

    const int pa[5] = {1, 0, 2, 1, 0};
    const int pb[5] = {0, 1, 0, 1, 2};

    for (int kt = 0; kt < KT_STEPS; kt++) {
        if (kt + 1 < KT_STEPS) {
            load_stage(kt + 1, (kt + 1) & 1);
            CP_WAIT1();
        } else {
            CP_WAIT0();
        }
        __syncthreads();

        const uint32_t As = sb + (kt & 1) * STAGE_B;
        const uint32_t Bs = As + 3 * TILE_B;

        // ---- main chain (0,0): C=0 HMMA + fp32 RN drain ----
#pragma unroll
        for (int ks = 0; ks < 4; ks++) {
            const uint32_t kx = (uint32_t)(ks << 5);
            uint32_t a[4][4], b[2][4];
#pragma unroll
            for (int mi = 0; mi < 4; mi++)
                ldsm4(a[mi], As + (swA[mi] ^ kx));
#pragma unroll
            for (int nh = 0; nh < 2; nh++)
                ldsm4(b[nh], Bs + (swB[nh] ^ kx));
#pragma unroll
            for (int mi = 0; mi < 4; mi++) {
#pragma unroll
                for (int ni = 0; ni < 4; ni++) {
                    float t[4];
                    const uint32_t bb0 = b[ni >> 1][(ni & 1) * 2];
                    const uint32_t bb1 = b[ni >> 1][(ni & 1) * 2 + 1];
                    mma16816_z(t, a[mi], bb0, bb1);
                    accH[mi][ni][0] += t[0];
                    accH[mi][ni][1] += t[1];
                    accH[mi][ni][2] += t[2];
                    accH[mi][ni][3] += t[3];
                }
            }
        }

        // ---- correction chains -> accL (chained) ----
        for (int p = 0; p < ncorr; p++) {
            const uint32_t at = As + pa[p] * TILE_B;
            const uint32_t bt = Bs + pb[p] * TILE_B;
#pragma unroll
            for (int ks = 0; ks < 4; ks++) {
                const uint32_t kx = (uint32_t)(ks << 5);
                uint32_t a[4][4], b[2][4];
#pragma unroll
                for (int mi = 0; mi < 4; mi++)
                    ldsm4(a[mi], at + (swA[mi] ^ kx));
#pragma unroll
                for (int nh = 0; nh < 2; nh++)
                    ldsm4(b[nh], bt + (swB[nh] ^ kx));
#pragma unroll
                for (int mi = 0; mi < 4; mi++) {
                    mma16816(accL[mi][0], a[mi], b[0][0], b[0][1]);
                    mma16816(accL[mi][1], a[mi], b[0][2], b[0][3]);
                    mma16816(accL[mi][2], a[mi], b[1][0], b[1][1]);
                    mma16816(accL[mi][3], a[mi], b[1][2], b[1][3]);
                }
            }
        }
        __syncthreads();
    }

#pragma unroll
    for (int mi = 0; mi < 4; mi++) {
        const int r0 = bm + wm * 64 + mi * 16 + (l >> 2);
#pragma unroll
        for (int ni = 0; ni < 4; ni++) {
            const int cb = bn + wn * 32 + ni * 8 + 2 * (l & 3);
            const float bx = bias[cb], by = bias[cb + 1];
            float2 v0 = make_float2(accH[mi][ni][0] + accL[mi][ni][0] + bx,
                                    accH[mi][ni][1] + accL[mi][ni][1] + by);
            float2 v1 = make_float2(accH[mi][ni][2] + accL[mi][ni][2] + bx,
                                    accH[mi][ni][3] + accL[mi][ni][3] + by);
            *(float2*)(C + (size_t)r0 * EE + cb) = v0;
            *(float2*)(C + (size_t)(r0 + 8) * EE + cb) = v1;
        }
    }
}

// ===========================================================================
// Flash attention, f32x2, 256 threads (R8 math, bitwise R1-class), now with
// cp.async double-buffered K/V stages (K from g_kT, V from g_v) so tile
// transfers overlap compute. Smem: Qs 32K | stage0 64K | stage1 64K | Pt 64K.
// Pipeline per tile: WAIT0 -> sync -> prefetch(kt+1) -> S/softmax/Pt -> sync
// -> PV. (prefetch into a stage is safe: the sync proves all warps finished
// the iteration that last read it.)
// ===========================================================================
#define AT_STG_W  8192                 // stage words: Ks 8192? (see below)
#define ATTN_SMEM (32768 + 2 * 65536 + 65536)   // 229376 bytes

__global__ __launch_bounds__(256, 1)
void attn2(float* __restrict__ Out)
{
    extern __shared__ float sm[];
    float* Qs = sm;                         // words 0..8191 (32KB, d-major swz)
    float* Pt = sm + 8192 + 2 * 16384;      // words 40960.. (64KB, c-major swz)
    float4* Qs4 = (float4*)Qs;
    float4* Pt4 = (float4*)Pt;
    const ulonglong2* Pt16 = (const ulonglong2*)Pt;
    const uint32_t sb = smem_u32(sm);

    const int b = blockIdx.z;
    const int h = blockIdx.y;
    const int q0 = blockIdx.x * 128;
    const int tid = threadIdx.x;
    const int g = tid & 15;
    const int w = tid >> 4;
    const size_t base = (size_t)b * SS * EE + (size_t)h * DD;
    const size_t ktbase = (size_t)(b * HH + h) * DD;   // g_kT row base

    // Load Q tile transposed (d-major) with XOR swizzle on r-blocks.
    for (int t = tid; t < 128 * 16; t += 256) {
        const int r  = t >> 4;
        const int d4 = (t & 15) << 2;
        const float4 v = *(const float4*)(g_q + base + (size_t)(q0 + r) * EE + d4);
        const int r4 = r >> 2, rm = r & 3;
        const int sd = (d4 >> 3) & 7;
        Qs[((d4 + 0) << 7) + ((r4 ^ sd) << 2) + rm] = v.x;
        Qs[((d4 + 1) << 7) + ((r4 ^ sd) << 2) + rm] = v.y;
        Qs[((d4 + 2) << 7) + ((r4 ^ sd) << 2) + rm] = v.z;
        Qs[((d4 + 3) << 7) + ((r4 ^ sd) << 2) + rm] = v.w;
    }

    // cp.async prefetch of tile kt into stage st.
    auto prefetch = [&](int kt, int st) {
        const uint32_t stage = sb + 32768 + st * 65536;
        // K: g_kT rows d=0..63, 128 keys -> d-major swizzled (same layout as R12)
#pragma unroll
        for (int i = 0; i < 8; i++) {
            const int idx = tid + i * 256;       // 0..2047
            const int d  = idx >> 5;
            const int r4 = idx & 31;
            const int sd = (d >> 3) & 7;
            const float* src = g_kT + (ktbase + d) * SS + kt * 128 + r4 * 4;
            CPASYNC16(stage + (uint32_t)(d * 512 + ((r4 ^ sd) << 4)), src);
        }
        // V: natural [r][64 floats]
#pragma unroll
        for (int i = 0; i < 8; i++) {
            const int idx = tid + i * 256;       // 0..2047
            const int r = idx >> 4;
            const int c = idx & 15;
            const float* src = g_v + base + (size_t)(kt * 128 + r) * EE + c * 4;
            CPASYNC16(stage + 32768u + (uint32_t)(r * 256 + c * 16), src);
        }
        CP_COMMIT();
    };
    prefetch(0, 0);

    float mrow[8], lrs[8];
    u64 o2[4][4];                   // q-row pairs x 4 d-cols
#pragma unroll
    for (int j = 0; j < 8; j++) { mrow[j] = -1e30f; lrs[j] = 0.0f; }
#pragma unroll
    for (int j2 = 0; j2 < 4; j2++)
#pragma unroll
        for (int dd = 0; dd < 4; dd++) o2[j2][dd] = 0ULL;

    for (int kt = 0; kt < SS / 128; kt++) {
        CP_WAIT0();            // own chunks of tile kt done (only pending group)
        __syncthreads();       // all warps' chunks visible; prev iteration done
        if (kt + 1 < SS / 128) prefetch(kt + 1, (kt + 1) & 1);

        const int st = kt & 1;
        const ulonglong2* Ks16 = (const ulonglong2*)(sm + 8192 + st * 16384);
        const float* Vs = sm + 8192 + st * 16384 + 8192;

        // ---- S^T tile: pairs along k; acc2[i2][j] ----
        u64 acc2[4][8];
#pragma unroll
        for (int i2 = 0; i2 < 4; i2++)
#pragma unroll
            for (int j = 0; j < 8; j++) acc2[i2][j] = 0ULL;

#pragma unroll 8
        for (int d = 0; d < 64; d++) {
            const int sd = (d >> 3) & 7;
            const ulonglong2 ka = Ks16[(d << 5) + ((g * 2) ^ sd)];
            const ulonglong2 kb = Ks16[(d << 5) + ((g * 2 + 1) ^ sd)];
            const float4 qa = Qs4[(d << 5) + ((w * 2) ^ sd)];
            const float4 qb = Qs4[(d << 5) + ((w * 2 + 1) ^ sd)];
            const u64 kp[4] = {ka.x, ka.y, kb.x, kb.y};
            const u64 qd[8] = {dup2(qa.x), dup2(qa.y), dup2(qa.z), dup2(qa.w),
                               dup2(qb.x), dup2(qb.y), dup2(qb.z), dup2(qb.w)};
#pragma unroll
            for (int i2 = 0; i2 < 4; i2++)
#pragma unroll
                for (int j = 0; j < 8; j++)
                    fma2(acc2[i2][j], kp[i2], qd[j]);
        }

        // Unpack (register aliasing) to Sf[i][j], i = k-col offset 0..7
        float Sf[8][8];
#pragma unroll
        for (int i2 = 0; i2 < 4; i2++)
#pragma unroll
            for (int j = 0; j < 8; j++)
                unpack2(Sf[2 * i2][j], Sf[2 * i2 + 1][j], acc2[i2][j]);

        // scores = floor(dot / 8)
#pragma unroll
        for (int i = 0; i < 8; i++)
#pragma unroll
            for (int j = 0; j < 8; j++)
                Sf[i][j] = floorf(Sf[i][j] * 0.125f);

        // Row max over the 128 k-cols of each q-row
        float mt[8];
#pragma unroll
        for (int j = 0; j < 8; j++) {
            float m = Sf[0][j];
#pragma unroll
            for (int i = 1; i < 8; i++) m = fmaxf(m, Sf[i][j]);
            mt[j] = m;
        }
#pragma unroll
        for (int off = 8; off >= 1; off >>= 1)
#pragma unroll
            for (int j = 0; j < 8; j++)
                mt[j] = fmaxf(mt[j], __shfl_xor_sync(0xffffffffu, mt[j], off));

        float scj[8], rs[8];
#pragma unroll
        for (int j = 0; j < 8; j++) {
            const float mn = fmaxf(mrow[j], mt[j]);
            scj[j] = __expf(mrow[j] - mn);   // 0 on first tile
            mrow[j] = mn;
            float s = 0.0f;
#pragma unroll
            for (int i = 0; i < 8; i++) {
                Sf[i][j] = __expf(Sf[i][j] - mn);
                s += Sf[i][j];
            }
            rs[j] = s;
        }
#pragma unroll
        for (int off = 8; off >= 1; off >>= 1)
#pragma unroll
            for (int j = 0; j < 8; j++)
                rs[j] += __shfl_xor_sync(0xffffffffu, rs[j], off);
#pragma unroll
        for (int j = 0; j < 8; j++)
            lrs[j] = lrs[j] * scj[j] + rs[j];
#pragma unroll
        for (int j2 = 0; j2 < 4; j2++) {
            const u64 sc2 = pack2(scj[2 * j2], scj[2 * j2 + 1]);
#pragma unroll
            for (int dd = 0; dd < 4; dd++)
                o2[j2][dd] = mul2(o2[j2][dd], sc2);
        }

        // Store P^T (c-major, q float4-contiguous, swizzled)
#pragma unroll
        for (int i = 0; i < 8; i++) {
            const int c = g * 8 + i;
            const int sw = g & 7;   // (c>>3)&7
            Pt4[(c << 5) + ((w * 2) ^ sw)] =
                make_float4(Sf[i][0], Sf[i][1], Sf[i][2], Sf[i][3]);
            Pt4[(c << 5) + ((w * 2 + 1) ^ sw)] =
                make_float4(Sf[i][4], Sf[i][5], Sf[i][6], Sf[i][7]);
        }
        __syncthreads();

        // O += P V; pairs along q: o2[j2][dd], rows (8w+2j2, +1), d = 4g+dd
#pragma unroll 8
        for (int k = 0; k < 128; k++) {
            const int sw = (k >> 3) & 7;
            const ulonglong2 pA = Pt16[(k << 5) + ((w * 2) ^ sw)];
            const ulonglong2 pB = Pt16[(k << 5) + ((w * 2 + 1) ^ sw)];
            const float4 vv = *(const float4*)&Vs[(k << 6) + (g << 2)];
            const u64 pp[4] = {pA.x, pA.y, pB.x, pB.y};
            const u64 vd[4] = {dup2(vv.x), dup2(vv.y), dup2(vv.z), dup2(vv.w)};
#pragma unroll
            for (int j2 = 0; j2 < 4; j2++)
#pragma unroll
                for (int dd = 0; dd < 4; dd++)
                    fma2(o2[j2][dd], pp[j2], vd[dd]);
        }
    }

    // Epilogue: normalize and store. Out col = h*64 + g*4 + dd
#pragma unroll
    for (int j = 0; j < 8; j++) {
        const int j2 = j >> 1;
        const float inv = 1.0f / lrs[j];
        float o[4];
#pragma unroll
        for (int dd = 0; dd < 4; dd++) {
            float lo, hi;
            unpack2(lo, hi, o2[j2][dd]);
            o[dd] = (j & 1) ? hi : lo;
        }
        const int r = q0 + w * 8 + j;
        *(float4*)(Out + base + (size_t)r * EE + (g << 2)) =
            make_float4(o[0] * inv, o[1] * inv, o[2] * inv, o[3] * inv);
    }
}

// ---------------------------------------------------------------------------
extern "C" void kernel_launch(void* const* d_in, const int* in_sizes, int n_in,
                              void* d_out, int out_size)
{
    const float* key   = (const float*)d_in[0];
    const float* query = (const float*)d_in[1];
    const float* value = (const float*)d_in[2];
    const float* Wq    = (const float*)d_in[3];
    const float* bq    = (const float*)d_in[4];
    const float* Wk    = (const float*)d_in[5];
    const float* bk    = (const float*)d_in[6];
    const float* Wv    = (const float*)d_in[7];
    const float* bv    = (const float*)d_in[8];
    float* out = (float*)d_out;

    void *pq = 0, *pk = 0, *pv = 0;
    cudaGetSymbolAddress(&pq, g_q);
    cudaGetSymbolAddress(&pk, g_k);
    cudaGetSymbolAddress(&pv, g_v);

    cudaFuncSetAttribute(proj_mma, cudaFuncAttributeMaxDynamicSharedMemorySize,
                         PROJ_SMEM);
    cudaFuncSetAttribute(attn2, cudaFuncAttributeMaxDynamicSharedMemorySize,
                         ATTN_SMEM);

    dim3 sgrid(MM * EE / 1024, 3);
    split_act<<<sgrid, 256>>>(query, key, value);
    dim3 wgrid(EE * EE / 1024, 3);
    split_w<<<wgrid, 256>>>(Wq, Wk, Wv);

    dim3 pgrid(EE / 128, MM / 128, 3);
    proj_mma<<<pgrid, 256, PROJ_SMEM>>>(bq, bk, bv,
                                        (float*)pq, (float*)pk, (float*)pv);

    dim3 tgrid(SS / 64, BB * HH);
    transpose_k<<<tgrid, 256>>>();

    dim3 agrid(SS / 128, HH, BB);
    attn2<<<agrid, 256, ATTN_SMEM>>>(out);
}